// round 2
// baseline (speedup 1.0000x reference)
#include <cuda_runtime.h>

#define NN 50000
#define EE 800000
#define GG 128
#define HH 128
#define LL 3
#define KK 3
#define EPSF 1e-5f

// ---------------- scratch (static device globals; no allocation) ----------------
__device__ float g_h [NN*HH];
__device__ float g_t1[NN*HH];
__device__ float g_t2[NN*HH];
__device__ float g_o [NN*HH];
__device__ float g_deg[NN];
__device__ int   g_src[EE];
__device__ int   g_dst[EE];
__device__ float g_we [EE];
__device__ float g_bnsum[HH];
__device__ float g_bnsq [HH];
__device__ float g_bnscale[HH];
__device__ float g_bnshift[HH];
__device__ double g_reg;
__device__ float g_gsum[GG*HH];
__device__ float g_gcnt[GG];

// ---------------- init ----------------
__global__ void k_init() {
    int i = blockIdx.x * blockDim.x + threadIdx.x;
    if (i < NN)      g_deg[i] = 0.f;
    if (i < GG*HH)   g_gsum[i] = 0.f;
    if (i < GG)      g_gcnt[i] = 0.f;
    if (i < HH)      { g_bnsum[i] = 0.f; g_bnsq[i] = 0.f; }
    if (i == 0)      g_reg = 0.0;
}

__global__ void k_zero4(float4* p) {
    int i = blockIdx.x * blockDim.x + threadIdx.x;
    p[i] = make_float4(0.f, 0.f, 0.f, 0.f);
}

__global__ void k_neg4(const float4* __restrict__ a, float4* __restrict__ b) {
    int i = blockIdx.x * blockDim.x + threadIdx.x;
    float4 v = a[i];
    b[i] = make_float4(-v.x, -v.y, -v.z, -v.w);
}

// ---------------- edge prep (edge_index arrives as int32 per harness dtype rules) ----------------
__global__ void k_edge_prep(const int* __restrict__ ei) {
    int e = blockIdx.x * blockDim.x + threadIdx.x;
    if (e >= EE) return;
    int s = ei[e];
    int d = ei[EE + e];
    g_src[e] = s;
    g_dst[e] = d;
    atomicAdd(&g_deg[s], 1.f);
}

__global__ void k_wedge() {
    int e = blockIdx.x * blockDim.x + threadIdx.x;
    if (e >= EE) return;
    int s = g_src[e], d = g_dst[e];
    float ds = g_deg[s], dd = g_deg[d];
    float is = ds > 0.f ? rsqrtf(fmaxf(ds, 1.f)) : 0.f;
    float id = dd > 0.f ? rsqrtf(fmaxf(dd, 1.f)) : 0.f;
    g_we[e] = -is * id;
}

// ---------------- node embed: x@W + b -> LayerNorm -> ReLU ----------------
__global__ void __launch_bounds__(256) k_embed(
    const float* __restrict__ x, const float* __restrict__ W,
    const float* __restrict__ b, const float* __restrict__ lng,
    const float* __restrict__ lnb)
{
    __shared__ float As[64][HH];
    int tx = threadIdx.x & 31, ty = threadIdx.x >> 5;
    int row0 = blockIdx.x * 64;

    for (int i = threadIdx.x; i < 64 * 32; i += 256) {
        int r = i >> 5, c4 = i & 31;
        float4 v = make_float4(0.f, 0.f, 0.f, 0.f);
        if (row0 + r < NN) v = ((const float4*)x)[(size_t)(row0 + r) * 32 + c4];
        ((float4*)&As[r][0])[c4] = v;
    }
    __syncthreads();

    float acc[8][4];
    #pragma unroll
    for (int rr = 0; rr < 8; rr++)
        { acc[rr][0]=0.f; acc[rr][1]=0.f; acc[rr][2]=0.f; acc[rr][3]=0.f; }

    const float4* W4 = (const float4*)W;
    #pragma unroll 4
    for (int k = 0; k < HH; k++) {
        float4 w = W4[k * 32 + tx];
        #pragma unroll
        for (int rr = 0; rr < 8; rr++) {
            float a = As[ty * 8 + rr][k];
            acc[rr][0] = fmaf(a, w.x, acc[rr][0]);
            acc[rr][1] = fmaf(a, w.y, acc[rr][1]);
            acc[rr][2] = fmaf(a, w.z, acc[rr][2]);
            acc[rr][3] = fmaf(a, w.w, acc[rr][3]);
        }
    }

    float4 bb = ((const float4*)b)[tx];
    float4 gg = ((const float4*)lng)[tx];
    float4 be = ((const float4*)lnb)[tx];

    #pragma unroll
    for (int rr = 0; rr < 8; rr++) {
        int row = row0 + ty * 8 + rr;
        float v0 = acc[rr][0] + bb.x;
        float v1 = acc[rr][1] + bb.y;
        float v2 = acc[rr][2] + bb.z;
        float v3 = acc[rr][3] + bb.w;
        float s  = v0 + v1 + v2 + v3;
        float sq = v0*v0 + v1*v1 + v2*v2 + v3*v3;
        #pragma unroll
        for (int off = 16; off > 0; off >>= 1) {
            s  += __shfl_xor_sync(0xffffffffu, s,  off);
            sq += __shfl_xor_sync(0xffffffffu, sq, off);
        }
        float mu  = s * (1.f / HH);
        float var = sq * (1.f / HH) - mu * mu;
        float rs  = rsqrtf(var + EPSF);
        float o0 = fmaxf((v0 - mu) * rs * gg.x + be.x, 0.f);
        float o1 = fmaxf((v1 - mu) * rs * gg.y + be.y, 0.f);
        float o2 = fmaxf((v2 - mu) * rs * gg.z + be.z, 0.f);
        float o3 = fmaxf((v3 - mu) * rs * gg.w + be.w, 0.f);
        if (row < NN)
            ((float4*)g_h)[(size_t)row * 32 + tx] = make_float4(o0, o1, o2, o3);
    }
}

// ---------------- spmm: y[dst] += factor * w_edge * h[src]; optional reg ----------------
template <bool REG>
__global__ void __launch_bounds__(256) k_spmm(
    const float* __restrict__ hin, float* __restrict__ y, float factor)
{
    int warp = (blockIdx.x * 256 + threadIdx.x) >> 5;
    if (warp >= EE) return;
    int lane = threadIdx.x & 31;
    int s = g_src[warp], d = g_dst[warp];
    float w = g_we[warp] * factor;
    float4 hv = ((const float4*)hin)[(size_t)s * 32 + lane];
    float* yp = &y[(size_t)d * HH + lane * 4];
    atomicAdd(yp + 0, w * hv.x);
    atomicAdd(yp + 1, w * hv.y);
    atomicAdd(yp + 2, w * hv.z);
    atomicAdd(yp + 3, w * hv.w);
    if (REG) {
        float4 hd = ((const float4*)hin)[(size_t)d * 32 + lane];
        float dx = hv.x - hd.x, dy = hv.y - hd.y;
        float dz = hv.z - hd.z, dw = hv.w - hd.w;
        float ss = dx*dx + dy*dy + dz*dz + dw*dw;
        #pragma unroll
        for (int off = 16; off > 0; off >>= 1)
            ss += __shfl_xor_sync(0xffffffffu, ss, off);
        if (lane == 0) atomicAdd(&g_reg, (double)ss);
    }
}

// reg-only edge pass (for the final hidden state)
__global__ void __launch_bounds__(256) k_regedge(const float* __restrict__ hin) {
    int warp = (blockIdx.x * 256 + threadIdx.x) >> 5;
    if (warp >= EE) return;
    int lane = threadIdx.x & 31;
    int s = g_src[warp], d = g_dst[warp];
    float4 hv = ((const float4*)hin)[(size_t)s * 32 + lane];
    float4 hd = ((const float4*)hin)[(size_t)d * 32 + lane];
    float dx = hv.x - hd.x, dy = hv.y - hd.y;
    float dz = hv.z - hd.z, dw = hv.w - hd.w;
    float ss = dx*dx + dy*dy + dz*dz + dw*dw;
    #pragma unroll
    for (int off = 16; off > 0; off >>= 1)
        ss += __shfl_xor_sync(0xffffffffu, ss, off);
    if (lane == 0) atomicAdd(&g_reg, (double)ss);
}

// ---------------- cheb gemm: out = h@W0 + t1@W1 + t2@W2 + b; accumulate BN stats ----------------
__global__ void __launch_bounds__(256) k_cheb(
    const float* __restrict__ W, const float* __restrict__ bias)
{
    __shared__ float As[64][HH];
    __shared__ float redS[8][HH];
    __shared__ float redQ[8][HH];
    int tx = threadIdx.x & 31, ty = threadIdx.x >> 5;
    int row0 = blockIdx.x * 64;

    float acc[8][4];
    #pragma unroll
    for (int rr = 0; rr < 8; rr++)
        { acc[rr][0]=0.f; acc[rr][1]=0.f; acc[rr][2]=0.f; acc[rr][3]=0.f; }

    const float* Amats[3] = { g_h, g_t1, g_t2 };

    for (int m = 0; m < 3; m++) {
        __syncthreads();
        const float* A = Amats[m];
        for (int i = threadIdx.x; i < 64 * 32; i += 256) {
            int r = i >> 5, c4 = i & 31;
            float4 v = make_float4(0.f, 0.f, 0.f, 0.f);
            if (row0 + r < NN) v = ((const float4*)A)[(size_t)(row0 + r) * 32 + c4];
            ((float4*)&As[r][0])[c4] = v;
        }
        __syncthreads();
        const float4* W4 = (const float4*)(W + (size_t)m * HH * HH);
        #pragma unroll 4
        for (int k = 0; k < HH; k++) {
            float4 w = W4[k * 32 + tx];
            #pragma unroll
            for (int rr = 0; rr < 8; rr++) {
                float a = As[ty * 8 + rr][k];
                acc[rr][0] = fmaf(a, w.x, acc[rr][0]);
                acc[rr][1] = fmaf(a, w.y, acc[rr][1]);
                acc[rr][2] = fmaf(a, w.z, acc[rr][2]);
                acc[rr][3] = fmaf(a, w.w, acc[rr][3]);
            }
        }
    }

    float4 bb = ((const float4*)bias)[tx];
    float ps[4] = {0.f,0.f,0.f,0.f};
    float pq[4] = {0.f,0.f,0.f,0.f};

    #pragma unroll
    for (int rr = 0; rr < 8; rr++) {
        int row = row0 + ty * 8 + rr;
        float v0 = acc[rr][0] + bb.x;
        float v1 = acc[rr][1] + bb.y;
        float v2 = acc[rr][2] + bb.z;
        float v3 = acc[rr][3] + bb.w;
        if (row < NN) {
            ((float4*)g_o)[(size_t)row * 32 + tx] = make_float4(v0, v1, v2, v3);
            ps[0]+=v0; ps[1]+=v1; ps[2]+=v2; ps[3]+=v3;
            pq[0]+=v0*v0; pq[1]+=v1*v1; pq[2]+=v2*v2; pq[3]+=v3*v3;
        }
    }

    __syncthreads();
    ((float4*)&redS[ty][0])[tx] = make_float4(ps[0], ps[1], ps[2], ps[3]);
    ((float4*)&redQ[ty][0])[tx] = make_float4(pq[0], pq[1], pq[2], pq[3]);
    __syncthreads();
    if (ty == 0) {
        #pragma unroll
        for (int i = 0; i < 4; i++) {
            int c = tx * 4 + i;
            float s = 0.f, q = 0.f;
            #pragma unroll
            for (int j = 0; j < 8; j++) { s += redS[j][c]; q += redQ[j][c]; }
            atomicAdd(&g_bnsum[c], s);
            atomicAdd(&g_bnsq[c], q);
        }
    }
}

// ---------------- BN finalize + apply ----------------
__global__ void k_bnfin(const float* __restrict__ bng, const float* __restrict__ bnb) {
    int c = threadIdx.x;
    float m = g_bnsum[c] * (1.f / NN);
    float v = g_bnsq[c] * (1.f / NN) - m * m;
    float sc = bng[c] * rsqrtf(v + EPSF);
    g_bnscale[c] = sc;
    g_bnshift[c] = bnb[c] - m * sc;
    g_bnsum[c] = 0.f;
    g_bnsq[c]  = 0.f;
}

__global__ void k_bnapply() {
    int i = blockIdx.x * blockDim.x + threadIdx.x;  // float4 index over NN*32
    int c4 = i & 31;
    float4 v  = ((const float4*)g_o)[i];
    float4 sc = ((const float4*)g_bnscale)[c4];
    float4 sh = ((const float4*)g_bnshift)[c4];
    float4 o;
    o.x = fmaxf(fmaf(v.x, sc.x, sh.x), 0.f);
    o.y = fmaxf(fmaf(v.y, sc.y, sh.y), 0.f);
    o.z = fmaxf(fmaf(v.z, sc.z, sh.z), 0.f);
    o.w = fmaxf(fmaf(v.w, sc.w, sh.w), 0.f);
    ((float4*)g_h)[i] = o;
}

// ---------------- global mean pool (batch arrives as int32) ----------------
__global__ void __launch_bounds__(256) k_pool(const int* __restrict__ batch) {
    int warp = (blockIdx.x * 256 + threadIdx.x) >> 5;
    if (warp >= NN) return;
    int lane = threadIdx.x & 31;
    int b = batch[warp];
    float4 hv = ((const float4*)g_h)[(size_t)warp * 32 + lane];
    float* gp = &g_gsum[(size_t)b * HH + lane * 4];
    atomicAdd(gp + 0, hv.x);
    atomicAdd(gp + 1, hv.y);
    atomicAdd(gp + 2, hv.z);
    atomicAdd(gp + 3, hv.w);
    if (lane == 0) atomicAdd(&g_gcnt[b], 1.f);
}

// ---------------- MLP head + output ----------------
__global__ void k_head(const float* __restrict__ w1, const float* __restrict__ b1,
                       const float* __restrict__ w2, const float* __restrict__ b2,
                       float* __restrict__ out, int out_size)
{
    __shared__ float gm[HH];
    __shared__ float zz[64];
    int g = blockIdx.x, t = threadIdx.x;
    float cnt = fmaxf(g_gcnt[g], 1.f);
    gm[t] = g_gsum[(size_t)g * HH + t] / cnt;
    __syncthreads();
    if (t < 64) {
        float a = b1[t];
        #pragma unroll 4
        for (int c = 0; c < HH; c++) a = fmaf(gm[c], w1[c * 64 + t], a);
        zz[t] = fmaxf(a, 0.f);
    }
    __syncthreads();
    if (t < 2) {
        float a = b2[t];
        #pragma unroll 4
        for (int k = 0; k < 64; k++) a = fmaf(zz[k], w2[k * 2 + t], a);
        out[g * 2 + t] = a;
    }
    if (g == 0 && t == 0 && out_size > 256)
        out[256] = (float)(g_reg / (4.0 * (double)EE));
}

// ---------------- launch ----------------
extern "C" void kernel_launch(void* const* d_in, const int* in_sizes, int n_in,
                              void* d_out, int out_size)
{
    const float* x      = (const float*)d_in[0];
    const float* w_in   = (const float*)d_in[1];
    const float* b_in   = (const float*)d_in[2];
    const float* ln_g   = (const float*)d_in[3];
    const float* ln_b   = (const float*)d_in[4];
    const float* cheb_w = (const float*)d_in[5];
    const float* cheb_b = (const float*)d_in[6];
    const float* bn_g   = (const float*)d_in[7];
    const float* bn_b   = (const float*)d_in[8];
    const float* w1     = (const float*)d_in[9];
    const float* b1     = (const float*)d_in[10];
    const float* w2     = (const float*)d_in[11];
    const float* b2     = (const float*)d_in[12];
    const int* ei       = (const int*)d_in[13];
    const int* batch    = (const int*)d_in[14];
    float* out = (float*)d_out;

    float *p_h, *p_t1, *p_t2;
    cudaGetSymbolAddress((void**)&p_h,  g_h);
    cudaGetSymbolAddress((void**)&p_t1, g_t1);
    cudaGetSymbolAddress((void**)&p_t2, g_t2);

    const int FV = NN * HH / 4;      // 1,600,000 float4s
    const int FB = FV / 256;         // 6250 blocks (exact)

    k_init<<<(NN + 255) / 256, 256>>>();
    k_edge_prep<<<EE / 256, 256>>>(ei);
    k_wedge<<<EE / 256, 256>>>();
    k_embed<<<(NN + 63) / 64, 256>>>(x, w_in, b_in, ln_g, ln_b);

    for (int l = 0; l < LL; l++) {
        k_zero4<<<FB, 256>>>((float4*)p_t1);
        k_spmm<true><<<EE / 8, 256>>>(p_h, p_t1, 1.0f);
        k_neg4<<<FB, 256>>>((const float4*)p_h, (float4*)p_t2);
        k_spmm<false><<<EE / 8, 256>>>(p_t1, p_t2, 2.0f);
        k_cheb<<<(NN + 63) / 64, 256>>>(cheb_w + (size_t)l * KK * HH * HH,
                                        cheb_b + (size_t)l * HH);
        k_bnfin<<<1, HH>>>(bn_g + (size_t)l * HH, bn_b + (size_t)l * HH);
        k_bnapply<<<FB, 256>>>();
    }

    k_regedge<<<EE / 8, 256>>>(p_h);
    k_pool<<<(NN * 32 + 255) / 256, 256>>>(batch);
    k_head<<<GG, HH>>>(w1, b1, w2, b2, out, out_size);
}

// round 3
// speedup vs baseline: 7.0227x; 7.0227x over previous
#include <cuda_runtime.h>

#define NN 50000
#define EE 800000
#define GG 128
#define HH 128
#define LL 3
#define KK 3
#define EPSF 1e-5f
#define SCAN_B 256
#define NBLK ((NN + SCAN_B - 1) / SCAN_B)   // 196

// ---------------- scratch (static device globals; no allocation) ----------------
__device__ float g_h [NN*HH];
__device__ float g_t1[NN*HH];
__device__ float g_t2[NN*HH];
__device__ float g_o [NN*HH];
__device__ int   g_src[EE];
__device__ int   g_dst[EE];
__device__ int   g_ecol[EE];     // CSR column (src) sorted by dst
__device__ float g_ew [EE];      // CSR edge weight
__device__ int   g_degi[NN];     // out-degree (indexed by src)
__device__ float g_dinv[NN];
__device__ int   g_cnt[NN];      // in-degree (indexed by dst)
__device__ int   g_incl[NN];     // inclusive scan scratch
__device__ int   g_bsum[SCAN_B];
__device__ int   g_bscan[SCAN_B];
__device__ int   g_rowptr[NN+1];
__device__ int   g_cur[NN];
__device__ float g_bnsum[HH];
__device__ float g_bnsq [HH];
__device__ float g_bnscale[HH];
__device__ float g_bnshift[HH];
__device__ double g_reg;
__device__ float g_gsum[GG*HH];
__device__ float g_gcnt[GG];

// ---------------- init ----------------
__global__ void k_init() {
    int i = blockIdx.x * blockDim.x + threadIdx.x;
    if (i < NN)    { g_degi[i] = 0; g_cnt[i] = 0; g_cur[i] = 0; }
    if (i < GG*HH)   g_gsum[i] = 0.f;
    if (i < GG)      g_gcnt[i] = 0.f;
    if (i < HH)    { g_bnsum[i] = 0.f; g_bnsq[i] = 0.f; }
    if (i == 0)      g_reg = 0.0;
}

// ---------------- edge prep (int32 indices per harness dtype rules) ----------------
__global__ void k_edge_prep(const int* __restrict__ ei) {
    int e = blockIdx.x * blockDim.x + threadIdx.x;
    if (e >= EE) return;
    int s = ei[e];
    int d = ei[EE + e];
    g_src[e] = s;
    g_dst[e] = d;
    atomicAdd(&g_degi[s], 1);
    atomicAdd(&g_cnt[d], 1);
}

__global__ void k_dinv() {
    int i = blockIdx.x * blockDim.x + threadIdx.x;
    if (i >= NN) return;
    int d = g_degi[i];
    g_dinv[i] = d > 0 ? rsqrtf((float)d) : 0.f;
}

// ---------------- 3-kernel exclusive scan of g_cnt -> g_rowptr ----------------
__global__ void k_scan1() {
    __shared__ int sm[SCAN_B];
    int i = blockIdx.x * SCAN_B + threadIdx.x;
    int v = (i < NN) ? g_cnt[i] : 0;
    sm[threadIdx.x] = v;
    __syncthreads();
    #pragma unroll
    for (int off = 1; off < SCAN_B; off <<= 1) {
        int t = (threadIdx.x >= off) ? sm[threadIdx.x - off] : 0;
        __syncthreads();
        sm[threadIdx.x] += t;
        __syncthreads();
    }
    if (i < NN) g_incl[i] = sm[threadIdx.x];
    if (threadIdx.x == SCAN_B - 1) g_bsum[blockIdx.x] = sm[threadIdx.x];
}

__global__ void k_scan2() {
    __shared__ int sm[SCAN_B];
    int t0 = threadIdx.x;
    sm[t0] = (t0 < NBLK) ? g_bsum[t0] : 0;
    __syncthreads();
    #pragma unroll
    for (int off = 1; off < SCAN_B; off <<= 1) {
        int t = (t0 >= off) ? sm[t0 - off] : 0;
        __syncthreads();
        sm[t0] += t;
        __syncthreads();
    }
    g_bscan[t0] = sm[t0];
}

__global__ void k_scan3() {
    int i = blockIdx.x * SCAN_B + threadIdx.x;
    if (i < NN) {
        int off = (blockIdx.x > 0) ? g_bscan[blockIdx.x - 1] : 0;
        g_rowptr[i] = g_incl[i] - g_cnt[i] + off;   // exclusive
    }
    if (i == 0) g_rowptr[NN] = EE;
}

__global__ void k_scatter() {
    int e = blockIdx.x * blockDim.x + threadIdx.x;
    if (e >= EE) return;
    int s = g_src[e], d = g_dst[e];
    int pos = g_rowptr[d] + atomicAdd(&g_cur[d], 1);
    g_ecol[pos] = s;
    g_ew[pos] = -g_dinv[s] * g_dinv[d];
}

// ---------------- node embed: x@W + b -> LayerNorm -> ReLU ----------------
__global__ void __launch_bounds__(256) k_embed(
    const float* __restrict__ x, const float* __restrict__ W,
    const float* __restrict__ b, const float* __restrict__ lng,
    const float* __restrict__ lnb)
{
    __shared__ float As[64][HH];
    int tx = threadIdx.x & 31, ty = threadIdx.x >> 5;
    int row0 = blockIdx.x * 64;

    for (int i = threadIdx.x; i < 64 * 32; i += 256) {
        int r = i >> 5, c4 = i & 31;
        float4 v = make_float4(0.f, 0.f, 0.f, 0.f);
        if (row0 + r < NN) v = ((const float4*)x)[(size_t)(row0 + r) * 32 + c4];
        ((float4*)&As[r][0])[c4] = v;
    }
    __syncthreads();

    float acc[8][4];
    #pragma unroll
    for (int rr = 0; rr < 8; rr++)
        { acc[rr][0]=0.f; acc[rr][1]=0.f; acc[rr][2]=0.f; acc[rr][3]=0.f; }

    const float4* W4 = (const float4*)W;
    #pragma unroll 4
    for (int k = 0; k < HH; k++) {
        float4 w = W4[k * 32 + tx];
        #pragma unroll
        for (int rr = 0; rr < 8; rr++) {
            float a = As[ty * 8 + rr][k];
            acc[rr][0] = fmaf(a, w.x, acc[rr][0]);
            acc[rr][1] = fmaf(a, w.y, acc[rr][1]);
            acc[rr][2] = fmaf(a, w.z, acc[rr][2]);
            acc[rr][3] = fmaf(a, w.w, acc[rr][3]);
        }
    }

    float4 bb = ((const float4*)b)[tx];
    float4 gg = ((const float4*)lng)[tx];
    float4 be = ((const float4*)lnb)[tx];

    #pragma unroll
    for (int rr = 0; rr < 8; rr++) {
        int row = row0 + ty * 8 + rr;
        float v0 = acc[rr][0] + bb.x;
        float v1 = acc[rr][1] + bb.y;
        float v2 = acc[rr][2] + bb.z;
        float v3 = acc[rr][3] + bb.w;
        float s  = v0 + v1 + v2 + v3;
        float sq = v0*v0 + v1*v1 + v2*v2 + v3*v3;
        #pragma unroll
        for (int off = 16; off > 0; off >>= 1) {
            s  += __shfl_xor_sync(0xffffffffu, s,  off);
            sq += __shfl_xor_sync(0xffffffffu, sq, off);
        }
        float mu  = s * (1.f / HH);
        float var = sq * (1.f / HH) - mu * mu;
        float rs  = rsqrtf(var + EPSF);
        float o0 = fmaxf((v0 - mu) * rs * gg.x + be.x, 0.f);
        float o1 = fmaxf((v1 - mu) * rs * gg.y + be.y, 0.f);
        float o2 = fmaxf((v2 - mu) * rs * gg.z + be.z, 0.f);
        float o3 = fmaxf((v3 - mu) * rs * gg.w + be.w, 0.f);
        if (row < NN)
            ((float4*)g_h)[(size_t)row * 32 + tx] = make_float4(o0, o1, o2, o3);
    }
}

// ---------------- CSR spmm #1: t1[d] = sum w*h[src]; fused Dirichlet reg ----------------
__global__ void __launch_bounds__(256) k_spmm1() {
    __shared__ float blk_ss[8];
    int warp = blockIdx.x * 8 + (threadIdx.x >> 5);
    int lane = threadIdx.x & 31;
    float ss = 0.f;
    if (warp < NN) {
        int beg = g_rowptr[warp], end = g_rowptr[warp + 1];
        float4 hd = ((const float4*)g_h)[(size_t)warp * 32 + lane];
        float4 acc = make_float4(0.f, 0.f, 0.f, 0.f);
        for (int e = beg; e < end; e++) {
            int s = g_ecol[e];
            float w = g_ew[e];
            float4 hv = ((const float4*)g_h)[(size_t)s * 32 + lane];
            acc.x = fmaf(w, hv.x, acc.x);
            acc.y = fmaf(w, hv.y, acc.y);
            acc.z = fmaf(w, hv.z, acc.z);
            acc.w = fmaf(w, hv.w, acc.w);
            float dx = hv.x - hd.x, dy = hv.y - hd.y;
            float dz = hv.z - hd.z, dw = hv.w - hd.w;
            ss = fmaf(dx, dx, ss); ss = fmaf(dy, dy, ss);
            ss = fmaf(dz, dz, ss); ss = fmaf(dw, dw, ss);
        }
        ((float4*)g_t1)[(size_t)warp * 32 + lane] = acc;
    }
    #pragma unroll
    for (int off = 16; off > 0; off >>= 1)
        ss += __shfl_xor_sync(0xffffffffu, ss, off);
    if (lane == 0) blk_ss[threadIdx.x >> 5] = ss;
    __syncthreads();
    if (threadIdx.x == 0) {
        double tot = 0.0;
        #pragma unroll
        for (int j = 0; j < 8; j++) tot += (double)blk_ss[j];
        atomicAdd(&g_reg, tot);
    }
}

// ---------------- CSR spmm #2: t2[d] = 2*sum w*t1[src] - h[d] ----------------
__global__ void __launch_bounds__(256) k_spmm2() {
    int warp = blockIdx.x * 8 + (threadIdx.x >> 5);
    if (warp >= NN) return;
    int lane = threadIdx.x & 31;
    int beg = g_rowptr[warp], end = g_rowptr[warp + 1];
    float4 acc = make_float4(0.f, 0.f, 0.f, 0.f);
    for (int e = beg; e < end; e++) {
        int s = g_ecol[e];
        float w = g_ew[e];
        float4 hv = ((const float4*)g_t1)[(size_t)s * 32 + lane];
        acc.x = fmaf(w, hv.x, acc.x);
        acc.y = fmaf(w, hv.y, acc.y);
        acc.z = fmaf(w, hv.z, acc.z);
        acc.w = fmaf(w, hv.w, acc.w);
    }
    float4 hd = ((const float4*)g_h)[(size_t)warp * 32 + lane];
    float4 o;
    o.x = 2.f * acc.x - hd.x;
    o.y = 2.f * acc.y - hd.y;
    o.z = 2.f * acc.z - hd.z;
    o.w = 2.f * acc.w - hd.w;
    ((float4*)g_t2)[(size_t)warp * 32 + lane] = o;
}

// ---------------- reg-only pass for the final hidden state ----------------
__global__ void __launch_bounds__(256) k_regedge() {
    __shared__ float blk_ss[8];
    int lane = threadIdx.x & 31;
    int wid  = blockIdx.x * 8 + (threadIdx.x >> 5);
    int nw   = gridDim.x * 8;
    float ss = 0.f;
    for (int e = wid; e < EE; e += nw) {
        int s = g_src[e], d = g_dst[e];
        float4 hv = ((const float4*)g_h)[(size_t)s * 32 + lane];
        float4 hd = ((const float4*)g_h)[(size_t)d * 32 + lane];
        float dx = hv.x - hd.x, dy = hv.y - hd.y;
        float dz = hv.z - hd.z, dw = hv.w - hd.w;
        ss = fmaf(dx, dx, ss); ss = fmaf(dy, dy, ss);
        ss = fmaf(dz, dz, ss); ss = fmaf(dw, dw, ss);
    }
    #pragma unroll
    for (int off = 16; off > 0; off >>= 1)
        ss += __shfl_xor_sync(0xffffffffu, ss, off);
    if (lane == 0) blk_ss[threadIdx.x >> 5] = ss;
    __syncthreads();
    if (threadIdx.x == 0) {
        double tot = 0.0;
        #pragma unroll
        for (int j = 0; j < 8; j++) tot += (double)blk_ss[j];
        atomicAdd(&g_reg, tot);
    }
}

// ---------------- cheb gemm: o = h@W0 + t1@W1 + t2@W2 + b; BN stats ----------------
__global__ void __launch_bounds__(256) k_cheb(
    const float* __restrict__ W, const float* __restrict__ bias)
{
    __shared__ float As[64][HH];
    __shared__ float redS[8][HH];
    __shared__ float redQ[8][HH];
    int tx = threadIdx.x & 31, ty = threadIdx.x >> 5;
    int row0 = blockIdx.x * 64;

    float acc[8][4];
    #pragma unroll
    for (int rr = 0; rr < 8; rr++)
        { acc[rr][0]=0.f; acc[rr][1]=0.f; acc[rr][2]=0.f; acc[rr][3]=0.f; }

    const float* Amats[3] = { g_h, g_t1, g_t2 };

    for (int m = 0; m < 3; m++) {
        __syncthreads();
        const float* A = Amats[m];
        for (int i = threadIdx.x; i < 64 * 32; i += 256) {
            int r = i >> 5, c4 = i & 31;
            float4 v = make_float4(0.f, 0.f, 0.f, 0.f);
            if (row0 + r < NN) v = ((const float4*)A)[(size_t)(row0 + r) * 32 + c4];
            ((float4*)&As[r][0])[c4] = v;
        }
        __syncthreads();
        const float4* W4 = (const float4*)(W + (size_t)m * HH * HH);
        #pragma unroll 4
        for (int k = 0; k < HH; k++) {
            float4 w = W4[k * 32 + tx];
            #pragma unroll
            for (int rr = 0; rr < 8; rr++) {
                float a = As[ty * 8 + rr][k];
                acc[rr][0] = fmaf(a, w.x, acc[rr][0]);
                acc[rr][1] = fmaf(a, w.y, acc[rr][1]);
                acc[rr][2] = fmaf(a, w.z, acc[rr][2]);
                acc[rr][3] = fmaf(a, w.w, acc[rr][3]);
            }
        }
    }

    float4 bb = ((const float4*)bias)[tx];
    float ps[4] = {0.f,0.f,0.f,0.f};
    float pq[4] = {0.f,0.f,0.f,0.f};

    #pragma unroll
    for (int rr = 0; rr < 8; rr++) {
        int row = row0 + ty * 8 + rr;
        float v0 = acc[rr][0] + bb.x;
        float v1 = acc[rr][1] + bb.y;
        float v2 = acc[rr][2] + bb.z;
        float v3 = acc[rr][3] + bb.w;
        if (row < NN) {
            ((float4*)g_o)[(size_t)row * 32 + tx] = make_float4(v0, v1, v2, v3);
            ps[0]+=v0; ps[1]+=v1; ps[2]+=v2; ps[3]+=v3;
            pq[0]+=v0*v0; pq[1]+=v1*v1; pq[2]+=v2*v2; pq[3]+=v3*v3;
        }
    }

    __syncthreads();
    ((float4*)&redS[ty][0])[tx] = make_float4(ps[0], ps[1], ps[2], ps[3]);
    ((float4*)&redQ[ty][0])[tx] = make_float4(pq[0], pq[1], pq[2], pq[3]);
    __syncthreads();
    if (ty == 0) {
        #pragma unroll
        for (int i = 0; i < 4; i++) {
            int c = tx * 4 + i;
            float s = 0.f, q = 0.f;
            #pragma unroll
            for (int j = 0; j < 8; j++) { s += redS[j][c]; q += redQ[j][c]; }
            atomicAdd(&g_bnsum[c], s);
            atomicAdd(&g_bnsq[c], q);
        }
    }
}

// ---------------- BN finalize + apply ----------------
__global__ void k_bnfin(const float* __restrict__ bng, const float* __restrict__ bnb) {
    int c = threadIdx.x;
    float m = g_bnsum[c] * (1.f / NN);
    float v = g_bnsq[c] * (1.f / NN) - m * m;
    float sc = bng[c] * rsqrtf(v + EPSF);
    g_bnscale[c] = sc;
    g_bnshift[c] = bnb[c] - m * sc;
    g_bnsum[c] = 0.f;
    g_bnsq[c]  = 0.f;
}

__global__ void k_bnapply() {
    int i = blockIdx.x * blockDim.x + threadIdx.x;  // float4 index over NN*32
    int c4 = i & 31;
    float4 v  = ((const float4*)g_o)[i];
    float4 sc = ((const float4*)g_bnscale)[c4];
    float4 sh = ((const float4*)g_bnshift)[c4];
    float4 o;
    o.x = fmaxf(fmaf(v.x, sc.x, sh.x), 0.f);
    o.y = fmaxf(fmaf(v.y, sc.y, sh.y), 0.f);
    o.z = fmaxf(fmaf(v.z, sc.z, sh.z), 0.f);
    o.w = fmaxf(fmaf(v.w, sc.w, sh.w), 0.f);
    ((float4*)g_h)[i] = o;
}

// ---------------- global mean pool (batch arrives as int32) ----------------
__global__ void __launch_bounds__(256) k_pool(const int* __restrict__ batch) {
    int warp = (blockIdx.x * 256 + threadIdx.x) >> 5;
    if (warp >= NN) return;
    int lane = threadIdx.x & 31;
    int b = batch[warp];
    float4 hv = ((const float4*)g_h)[(size_t)warp * 32 + lane];
    float* gp = &g_gsum[(size_t)b * HH + lane * 4];
    atomicAdd(gp + 0, hv.x);
    atomicAdd(gp + 1, hv.y);
    atomicAdd(gp + 2, hv.z);
    atomicAdd(gp + 3, hv.w);
    if (lane == 0) atomicAdd(&g_gcnt[b], 1.f);
}

// ---------------- MLP head + output ----------------
__global__ void k_head(const float* __restrict__ w1, const float* __restrict__ b1,
                       const float* __restrict__ w2, const float* __restrict__ b2,
                       float* __restrict__ out, int out_size)
{
    __shared__ float gm[HH];
    __shared__ float zz[64];
    int g = blockIdx.x, t = threadIdx.x;
    float cnt = fmaxf(g_gcnt[g], 1.f);
    gm[t] = g_gsum[(size_t)g * HH + t] / cnt;
    __syncthreads();
    if (t < 64) {
        float a = b1[t];
        #pragma unroll 4
        for (int c = 0; c < HH; c++) a = fmaf(gm[c], w1[c * 64 + t], a);
        zz[t] = fmaxf(a, 0.f);
    }
    __syncthreads();
    if (t < 2) {
        float a = b2[t];
        #pragma unroll 4
        for (int k = 0; k < 64; k++) a = fmaf(zz[k], w2[k * 2 + t], a);
        out[g * 2 + t] = a;
    }
    if (g == 0 && t == 0 && out_size > 256)
        out[256] = (float)(g_reg / (4.0 * (double)EE));
}

// ---------------- launch ----------------
extern "C" void kernel_launch(void* const* d_in, const int* in_sizes, int n_in,
                              void* d_out, int out_size)
{
    const float* x      = (const float*)d_in[0];
    const float* w_in   = (const float*)d_in[1];
    const float* b_in   = (const float*)d_in[2];
    const float* ln_g   = (const float*)d_in[3];
    const float* ln_b   = (const float*)d_in[4];
    const float* cheb_w = (const float*)d_in[5];
    const float* cheb_b = (const float*)d_in[6];
    const float* bn_g   = (const float*)d_in[7];
    const float* bn_b   = (const float*)d_in[8];
    const float* w1     = (const float*)d_in[9];
    const float* b1     = (const float*)d_in[10];
    const float* w2     = (const float*)d_in[11];
    const float* b2     = (const float*)d_in[12];
    const int* ei       = (const int*)d_in[13];
    const int* batch    = (const int*)d_in[14];
    float* out = (float*)d_out;

    const int FV = NN * HH / 4;
    const int FB = FV / 256;             // 6250 (exact)
    const int NODE_WARP_BLKS = (NN + 7) / 8;  // 6250

    k_init<<<(NN + 255) / 256, 256>>>();
    k_edge_prep<<<EE / 256, 256>>>(ei);
    k_dinv<<<(NN + 255) / 256, 256>>>();
    k_scan1<<<NBLK, SCAN_B>>>();
    k_scan2<<<1, SCAN_B>>>();
    k_scan3<<<NBLK, SCAN_B>>>();
    k_scatter<<<EE / 256, 256>>>();

    k_embed<<<(NN + 63) / 64, 256>>>(x, w_in, b_in, ln_g, ln_b);

    for (int l = 0; l < LL; l++) {
        k_spmm1<<<NODE_WARP_BLKS, 256>>>();
        k_spmm2<<<NODE_WARP_BLKS, 256>>>();
        k_cheb<<<(NN + 63) / 64, 256>>>(cheb_w + (size_t)l * KK * HH * HH,
                                        cheb_b + (size_t)l * HH);
        k_bnfin<<<1, HH>>>(bn_g + (size_t)l * HH, bn_b + (size_t)l * HH);
        k_bnapply<<<FB, 256>>>();
    }

    k_regedge<<<1024, 256>>>();
    k_pool<<<(NN * 32 + 255) / 256, 256>>>(batch);
    k_head<<<GG, HH>>>(w1, b1, w2, b2, out, out_size);
}

// round 5
// speedup vs baseline: 8.0488x; 1.1461x over previous
#include <cuda_runtime.h>
#include <cstdint>

#define NN 50000
#define EE 800000
#define GG 128
#define HH 128
#define LL 3
#define KK 3
#define EPSF 1e-5f
#define SCAN_B 256
#define NBLK ((NN + SCAN_B - 1) / SCAN_B)   // 196
#define NTILE ((NN + 127) / 128)            // 391

// ---------------- scratch (static device globals; no allocation) ----------------
__device__ float g_h [NN*HH];
__device__ float g_t1[NN*HH];
__device__ float g_t2[NN*HH];
__device__ float g_o [NN*HH];
__device__ int   g_src[EE];
__device__ int   g_dst[EE];
__device__ int   g_ecol[EE];
__device__ float g_ew [EE];
__device__ int   g_degi[NN];
__device__ float g_dinv[NN];
__device__ int   g_cnt[NN];
__device__ int   g_incl[NN];
__device__ int   g_bsum[SCAN_B];
__device__ int   g_bscan[SCAN_B];
__device__ int   g_rowptr[NN+1];
__device__ int   g_cur[NN];
__device__ float g_bnsum[HH];
__device__ float g_bnsq [HH];
__device__ float g_bnscale[HH];
__device__ float g_bnshift[HH];
__device__ double g_reg;
__device__ float g_gsum[GG*HH];
__device__ float g_gcnt[GG];

// ================= helpers =================
__device__ __forceinline__ uint32_t f2tf32(float f) {
    uint32_t r;
    asm("cvt.rna.tf32.f32 %0, %1;" : "=r"(r) : "f"(f));
    return r;
}

// D += A(16x8,row) * B(8x8,col)  tf32 inputs, f32 accum
__device__ __forceinline__ void mma_tf32(float* d, const uint32_t* a, const uint32_t* b) {
    asm volatile(
        "mma.sync.aligned.m16n8k8.row.col.f32.tf32.tf32.f32 "
        "{%0,%1,%2,%3}, {%4,%5,%6,%7}, {%8,%9}, {%0,%1,%2,%3};"
        : "+f"(d[0]), "+f"(d[1]), "+f"(d[2]), "+f"(d[3])
        : "r"(a[0]), "r"(a[1]), "r"(a[2]), "r"(a[3]), "r"(b[0]), "r"(b[1]));
}

// smem layout (uint32 units)
#define AS_PITCH 36
#define BS_PITCH 132
#define ST_PITCH 129
#define OFF_AS   0
#define OFF_BS   (128*AS_PITCH)                 // 4608
#define OFF_STAGE 0                              // overlaps As/Bs (after sync)
#define OFF_EXTRA (128*ST_PITCH)                 // 16512 : sCs/sCq/bias/ln...
#define SMEM_U32 (OFF_EXTRA + 128*6)
#define SMEM_DYN (SMEM_U32*4)                    // ~69 KB

// load A chunk [128 rows x 32 k] as tf32 into As[128][36]; zero-pad rows >= NN
__device__ __forceinline__ void load_A32(
    uint32_t* As, const float* __restrict__ src, int row0, int kc)
{
    const float4* s4 = (const float4*)src;
    for (int idx = threadIdx.x; idx < 128 * 8; idx += 256) {
        int r = idx >> 3, c4 = idx & 7;
        float4 v = make_float4(0.f, 0.f, 0.f, 0.f);
        if (row0 + r < NN) v = s4[(size_t)(row0 + r) * 32 + kc * 8 + c4];
        uint32_t* p = As + r * AS_PITCH + c4 * 4;
        p[0] = f2tf32(v.x); p[1] = f2tf32(v.y);
        p[2] = f2tf32(v.z); p[3] = f2tf32(v.w);
    }
}

// load W chunk [32 k x 128 n] as tf32 into Bs[32][132]
__device__ __forceinline__ void load_B32(
    uint32_t* Bs, const float* __restrict__ W, int kc)
{
    const float4* s4 = (const float4*)W;
    for (int idx = threadIdx.x; idx < 32 * 32; idx += 256) {
        int r = idx >> 5, c4 = idx & 31;
        float4 v = s4[(size_t)(kc * 32 + r) * 32 + c4];
        uint32_t* p = Bs + r * BS_PITCH + c4 * 4;
        p[0] = f2tf32(v.x); p[1] = f2tf32(v.y);
        p[2] = f2tf32(v.z); p[3] = f2tf32(v.w);
    }
}

// one 32-wide K chunk of MMAs
__device__ __forceinline__ void mma_chunk(
    const uint32_t* As, const uint32_t* Bs,
    float acc[2][8][4], int m0, int n0, int g, int t)
{
    #pragma unroll
    for (int ks = 0; ks < 4; ks++) {
        int k0 = ks * 8;
        uint32_t a[2][4];
        #pragma unroll
        for (int mf = 0; mf < 2; mf++) {
            int r = m0 + mf * 16 + g;
            a[mf][0] = As[r * AS_PITCH + k0 + t];
            a[mf][1] = As[(r + 8) * AS_PITCH + k0 + t];
            a[mf][2] = As[r * AS_PITCH + k0 + t + 4];
            a[mf][3] = As[(r + 8) * AS_PITCH + k0 + t + 4];
        }
        #pragma unroll
        for (int nf = 0; nf < 8; nf++) {
            int c = n0 + nf * 8 + g;
            uint32_t b[2];
            b[0] = Bs[(k0 + t) * BS_PITCH + c];
            b[1] = Bs[(k0 + t + 4) * BS_PITCH + c];
            mma_tf32(acc[0][nf], a[0], b);
            mma_tf32(acc[1][nf], a[1], b);
        }
    }
}

// scatter warp accumulators into stage[128][129] with bias added
__device__ __forceinline__ void acc_to_stage(
    float* stage, const float* biasS, float acc[2][8][4],
    int m0, int n0, int g, int t)
{
    #pragma unroll
    for (int mf = 0; mf < 2; mf++) {
        #pragma unroll
        for (int nf = 0; nf < 8; nf++) {
            int c = n0 + nf * 8 + 2 * t;
            int r = m0 + mf * 16 + g;
            stage[r * ST_PITCH + c]           = acc[mf][nf][0] + biasS[c];
            stage[r * ST_PITCH + c + 1]       = acc[mf][nf][1] + biasS[c + 1];
            stage[(r + 8) * ST_PITCH + c]     = acc[mf][nf][2] + biasS[c];
            stage[(r + 8) * ST_PITCH + c + 1] = acc[mf][nf][3] + biasS[c + 1];
        }
    }
}

// ---------------- init ----------------
__global__ void k_init() {
    int i = blockIdx.x * blockDim.x + threadIdx.x;
    if (i < NN)    { g_degi[i] = 0; g_cnt[i] = 0; g_cur[i] = 0; }
    if (i < GG*HH)   g_gsum[i] = 0.f;
    if (i < GG)      g_gcnt[i] = 0.f;
    if (i < HH)    { g_bnsum[i] = 0.f; g_bnsq[i] = 0.f; }
    if (i == 0)      g_reg = 0.0;
}

// ---------------- edge prep ----------------
__global__ void k_edge_prep(const int* __restrict__ ei) {
    int e = blockIdx.x * blockDim.x + threadIdx.x;
    if (e >= EE) return;
    int s = ei[e];
    int d = ei[EE + e];
    g_src[e] = s;
    g_dst[e] = d;
    atomicAdd(&g_degi[s], 1);
    atomicAdd(&g_cnt[d], 1);
}

__global__ void k_dinv() {
    int i = blockIdx.x * blockDim.x + threadIdx.x;
    if (i >= NN) return;
    int d = g_degi[i];
    g_dinv[i] = d > 0 ? rsqrtf((float)d) : 0.f;
}

// ---------------- scan ----------------
__global__ void k_scan1() {
    __shared__ int sm[SCAN_B];
    int i = blockIdx.x * SCAN_B + threadIdx.x;
    int v = (i < NN) ? g_cnt[i] : 0;
    sm[threadIdx.x] = v;
    __syncthreads();
    #pragma unroll
    for (int off = 1; off < SCAN_B; off <<= 1) {
        int t = (threadIdx.x >= off) ? sm[threadIdx.x - off] : 0;
        __syncthreads();
        sm[threadIdx.x] += t;
        __syncthreads();
    }
    if (i < NN) g_incl[i] = sm[threadIdx.x];
    if (threadIdx.x == SCAN_B - 1) g_bsum[blockIdx.x] = sm[threadIdx.x];
}

__global__ void k_scan2() {
    __shared__ int sm[SCAN_B];
    int t0 = threadIdx.x;
    sm[t0] = (t0 < NBLK) ? g_bsum[t0] : 0;
    __syncthreads();
    #pragma unroll
    for (int off = 1; off < SCAN_B; off <<= 1) {
        int t = (t0 >= off) ? sm[t0 - off] : 0;
        __syncthreads();
        sm[t0] += t;
        __syncthreads();
    }
    g_bscan[t0] = sm[t0];
}

__global__ void k_scan3() {
    int i = blockIdx.x * SCAN_B + threadIdx.x;
    if (i < NN) {
        int off = (blockIdx.x > 0) ? g_bscan[blockIdx.x - 1] : 0;
        g_rowptr[i] = g_incl[i] - g_cnt[i] + off;
    }
    if (i == 0) g_rowptr[NN] = EE;
}

__global__ void k_scatter() {
    int e = blockIdx.x * blockDim.x + threadIdx.x;
    if (e >= EE) return;
    int s = g_src[e], d = g_dst[e];
    int pos = g_rowptr[d] + atomicAdd(&g_cur[d], 1);
    g_ecol[pos] = s;
    g_ew[pos] = -g_dinv[s] * g_dinv[d];
}

// ---------------- embed: x@W + b -> LayerNorm -> ReLU  (tf32 mma) ----------------
__global__ void __launch_bounds__(256) k_embed_mma(
    const float* __restrict__ x, const float* __restrict__ W,
    const float* __restrict__ b_in, const float* __restrict__ lng,
    const float* __restrict__ lnb)
{
    extern __shared__ uint32_t smem[];
    uint32_t* As = smem + OFF_AS;
    uint32_t* Bs = smem + OFF_BS;
    float* stage = (float*)(smem + OFF_STAGE);
    float* biasS = (float*)(smem + OFF_EXTRA);
    float* lngS  = biasS + 128;
    float* lnbS  = lngS + 128;
    float* muS   = lnbS + 128;
    float* rsS   = muS + 128;

    int tid = threadIdx.x;
    int lane = tid & 31, warp = tid >> 5;
    int g = lane >> 2, t = lane & 3;
    int m0 = (warp >> 1) * 32, n0 = (warp & 1) * 64;
    int row0 = blockIdx.x * 128;

    if (tid < 128) {
        biasS[tid] = b_in[tid];
        lngS[tid]  = lng[tid];
        lnbS[tid]  = lnb[tid];
    }

    float acc[2][8][4];
    #pragma unroll
    for (int i = 0; i < 2; i++)
        #pragma unroll
        for (int j = 0; j < 8; j++)
            { acc[i][j][0]=0.f; acc[i][j][1]=0.f; acc[i][j][2]=0.f; acc[i][j][3]=0.f; }

    for (int kc = 0; kc < 4; kc++) {
        __syncthreads();
        load_A32(As, x, row0, kc);
        load_B32(Bs, W, kc);
        __syncthreads();
        mma_chunk(As, Bs, acc, m0, n0, g, t);
    }

    __syncthreads();
    acc_to_stage(stage, biasS, acc, m0, n0, g, t);
    __syncthreads();

    if (tid < 128) {
        float s = 0.f, sq = 0.f;
        #pragma unroll 8
        for (int c = 0; c < HH; c++) {
            float v = stage[tid * ST_PITCH + c];
            s += v; sq = fmaf(v, v, sq);
        }
        float mu  = s * (1.f / HH);
        float var = sq * (1.f / HH) - mu * mu;
        muS[tid] = mu;
        rsS[tid] = rsqrtf(var + EPSF);
    }
    __syncthreads();

    for (int idx = tid; idx < 128 * HH; idx += 256) {
        int r = idx >> 7, c = idx & 127;
        if (row0 + r < NN) {
            float v = stage[r * ST_PITCH + c];
            v = (v - muS[r]) * rsS[r] * lngS[c] + lnbS[c];
            g_h[(size_t)(row0 + r) * HH + c] = fmaxf(v, 0.f);
        }
    }
}

// ---------------- cheb: g_o = h@W0 + t1@W1 + t2@W2 + b; fused BN stats ----------------
__global__ void __launch_bounds__(256) k_cheb_mma(
    const float* __restrict__ W, const float* __restrict__ bias)
{
    extern __shared__ uint32_t smem[];
    uint32_t* As = smem + OFF_AS;
    uint32_t* Bs = smem + OFF_BS;
    float* stage = (float*)(smem + OFF_STAGE);
    float* biasS = (float*)(smem + OFF_EXTRA);
    float* sCs   = biasS + 128;
    float* sCq   = sCs + 128;

    int tid = threadIdx.x;
    int lane = tid & 31, warp = tid >> 5;
    int g = lane >> 2, t = lane & 3;
    int m0 = (warp >> 1) * 32, n0 = (warp & 1) * 64;
    int row0 = blockIdx.x * 128;

    if (tid < 128) { biasS[tid] = bias[tid]; sCs[tid] = 0.f; sCq[tid] = 0.f; }

    float acc[2][8][4];
    #pragma unroll
    for (int i = 0; i < 2; i++)
        #pragma unroll
        for (int j = 0; j < 8; j++)
            { acc[i][j][0]=0.f; acc[i][j][1]=0.f; acc[i][j][2]=0.f; acc[i][j][3]=0.f; }

    const float* Asrc[3] = { g_h, g_t1, g_t2 };
    for (int m = 0; m < 3; m++) {
        for (int kc = 0; kc < 4; kc++) {
            __syncthreads();
            load_A32(As, Asrc[m], row0, kc);
            load_B32(Bs, W + (size_t)m * HH * HH, kc);
            __syncthreads();
            mma_chunk(As, Bs, acc, m0, n0, g, t);
        }
    }

    __syncthreads();
    acc_to_stage(stage, biasS, acc, m0, n0, g, t);
    __syncthreads();

    // store + per-column BN partials (each thread owns column c = tid & 127)
    {
        float ps = 0.f, pq = 0.f;
        int c = tid & 127;
        int rbase = tid >> 7;
        #pragma unroll 4
        for (int k = 0; k < 64; k++) {
            int r = rbase + k * 2;
            int row = row0 + r;
            if (row < NN) {
                float v = stage[r * ST_PITCH + c];
                g_o[(size_t)row * HH + c] = v;
                ps += v; pq = fmaf(v, v, pq);
            }
        }
        atomicAdd(&sCs[c], ps);
        atomicAdd(&sCq[c], pq);
    }
    __syncthreads();
    if (tid < 128) {
        atomicAdd(&g_bnsum[tid], sCs[tid]);
        atomicAdd(&g_bnsq[tid],  sCq[tid]);
    }
}

// ---------------- CSR spmm #1: t1 = L_hat h; fused Dirichlet reg ----------------
__global__ void __launch_bounds__(256) k_spmm1() {
    __shared__ float blk_ss[8];
    int warp = blockIdx.x * 8 + (threadIdx.x >> 5);
    int lane = threadIdx.x & 31;
    float ss = 0.f;
    if (warp < NN) {
        int beg = g_rowptr[warp], end = g_rowptr[warp + 1];
        float4 hd = ((const float4*)g_h)[(size_t)warp * 32 + lane];
        float4 acc = make_float4(0.f, 0.f, 0.f, 0.f);
        for (int e = beg; e < end; e++) {
            int s = g_ecol[e];
            float w = g_ew[e];
            float4 hv = ((const float4*)g_h)[(size_t)s * 32 + lane];
            acc.x = fmaf(w, hv.x, acc.x);
            acc.y = fmaf(w, hv.y, acc.y);
            acc.z = fmaf(w, hv.z, acc.z);
            acc.w = fmaf(w, hv.w, acc.w);
            float dx = hv.x - hd.x, dy = hv.y - hd.y;
            float dz = hv.z - hd.z, dw = hv.w - hd.w;
            ss = fmaf(dx, dx, ss); ss = fmaf(dy, dy, ss);
            ss = fmaf(dz, dz, ss); ss = fmaf(dw, dw, ss);
        }
        ((float4*)g_t1)[(size_t)warp * 32 + lane] = acc;
    }
    #pragma unroll
    for (int off = 16; off > 0; off >>= 1)
        ss += __shfl_xor_sync(0xffffffffu, ss, off);
    if (lane == 0) blk_ss[threadIdx.x >> 5] = ss;
    __syncthreads();
    if (threadIdx.x == 0) {
        double tot = 0.0;
        #pragma unroll
        for (int j = 0; j < 8; j++) tot += (double)blk_ss[j];
        atomicAdd(&g_reg, tot);
    }
}

// ---------------- CSR spmm #2: t2 = 2 L_hat t1 - h ----------------
__global__ void __launch_bounds__(256) k_spmm2() {
    int warp = blockIdx.x * 8 + (threadIdx.x >> 5);
    if (warp >= NN) return;
    int lane = threadIdx.x & 31;
    int beg = g_rowptr[warp], end = g_rowptr[warp + 1];
    float4 acc = make_float4(0.f, 0.f, 0.f, 0.f);
    for (int e = beg; e < end; e++) {
        int s = g_ecol[e];
        float w = g_ew[e];
        float4 hv = ((const float4*)g_t1)[(size_t)s * 32 + lane];
        acc.x = fmaf(w, hv.x, acc.x);
        acc.y = fmaf(w, hv.y, acc.y);
        acc.z = fmaf(w, hv.z, acc.z);
        acc.w = fmaf(w, hv.w, acc.w);
    }
    float4 hd = ((const float4*)g_h)[(size_t)warp * 32 + lane];
    float4 o;
    o.x = 2.f * acc.x - hd.x;
    o.y = 2.f * acc.y - hd.y;
    o.z = 2.f * acc.z - hd.z;
    o.w = 2.f * acc.w - hd.w;
    ((float4*)g_t2)[(size_t)warp * 32 + lane] = o;
}

// ---------------- reg-only pass for the final hidden state ----------------
__global__ void __launch_bounds__(256) k_regedge() {
    __shared__ float blk_ss[8];
    int lane = threadIdx.x & 31;
    int wid  = blockIdx.x * 8 + (threadIdx.x >> 5);
    int nw   = gridDim.x * 8;
    float ss = 0.f;
    for (int e = wid; e < EE; e += nw) {
        int s = g_src[e], d = g_dst[e];
        float4 hv = ((const float4*)g_h)[(size_t)s * 32 + lane];
        float4 hd = ((const float4*)g_h)[(size_t)d * 32 + lane];
        float dx = hv.x - hd.x, dy = hv.y - hd.y;
        float dz = hv.z - hd.z, dw = hv.w - hd.w;
        ss = fmaf(dx, dx, ss); ss = fmaf(dy, dy, ss);
        ss = fmaf(dz, dz, ss); ss = fmaf(dw, dw, ss);
    }
    #pragma unroll
    for (int off = 16; off > 0; off >>= 1)
        ss += __shfl_xor_sync(0xffffffffu, ss, off);
    if (lane == 0) blk_ss[threadIdx.x >> 5] = ss;
    __syncthreads();
    if (threadIdx.x == 0) {
        double tot = 0.0;
        #pragma unroll
        for (int j = 0; j < 8; j++) tot += (double)blk_ss[j];
        atomicAdd(&g_reg, tot);
    }
}

// ---------------- BN finalize + apply ----------------
__global__ void k_bnfin(const float* __restrict__ bng, const float* __restrict__ bnb) {
    int c = threadIdx.x;
    float m = g_bnsum[c] * (1.f / NN);
    float v = g_bnsq[c] * (1.f / NN) - m * m;
    float sc = bng[c] * rsqrtf(v + EPSF);
    g_bnscale[c] = sc;
    g_bnshift[c] = bnb[c] - m * sc;
    g_bnsum[c] = 0.f;
    g_bnsq[c]  = 0.f;
}

__global__ void k_bnapply() {
    int i = blockIdx.x * blockDim.x + threadIdx.x;
    int c4 = i & 31;
    float4 v  = ((const float4*)g_o)[i];
    float4 sc = ((const float4*)g_bnscale)[c4];
    float4 sh = ((const float4*)g_bnshift)[c4];
    float4 o;
    o.x = fmaxf(fmaf(v.x, sc.x, sh.x), 0.f);
    o.y = fmaxf(fmaf(v.y, sc.y, sh.y), 0.f);
    o.z = fmaxf(fmaf(v.z, sc.z, sh.z), 0.f);
    o.w = fmaxf(fmaf(v.w, sc.w, sh.w), 0.f);
    ((float4*)g_h)[i] = o;
}

// ---------------- global mean pool ----------------
__global__ void __launch_bounds__(256) k_pool(const int* __restrict__ batch) {
    int warp = (blockIdx.x * 256 + threadIdx.x) >> 5;
    if (warp >= NN) return;
    int lane = threadIdx.x & 31;
    int b = batch[warp];
    float4 hv = ((const float4*)g_h)[(size_t)warp * 32 + lane];
    float* gp = &g_gsum[(size_t)b * HH + lane * 4];
    atomicAdd(gp + 0, hv.x);
    atomicAdd(gp + 1, hv.y);
    atomicAdd(gp + 2, hv.z);
    atomicAdd(gp + 3, hv.w);
    if (lane == 0) atomicAdd(&g_gcnt[b], 1.f);
}

// ---------------- MLP head + output ----------------
__global__ void k_head(const float* __restrict__ w1, const float* __restrict__ b1,
                       const float* __restrict__ w2, const float* __restrict__ b2,
                       float* __restrict__ out, int out_size)
{
    __shared__ float gm[HH];
    __shared__ float zz[64];
    int g = blockIdx.x, t = threadIdx.x;
    float cnt = fmaxf(g_gcnt[g], 1.f);
    gm[t] = g_gsum[(size_t)g * HH + t] / cnt;
    __syncthreads();
    if (t < 64) {
        float a = b1[t];
        #pragma unroll 4
        for (int c = 0; c < HH; c++) a = fmaf(gm[c], w1[c * 64 + t], a);
        zz[t] = fmaxf(a, 0.f);
    }
    __syncthreads();
    if (t < 2) {
        float a = b2[t];
        #pragma unroll 4
        for (int k = 0; k < 64; k++) a = fmaf(zz[k], w2[k * 2 + t], a);
        out[g * 2 + t] = a;
    }
    if (g == 0 && t == 0 && out_size > 256)
        out[256] = (float)(g_reg / (4.0 * (double)EE));
}

// ---------------- launch ----------------
extern "C" void kernel_launch(void* const* d_in, const int* in_sizes, int n_in,
                              void* d_out, int out_size)
{
    const float* x      = (const float*)d_in[0];
    const float* w_in   = (const float*)d_in[1];
    const float* b_in   = (const float*)d_in[2];
    const float* ln_g   = (const float*)d_in[3];
    const float* ln_b   = (const float*)d_in[4];
    const float* cheb_w = (const float*)d_in[5];
    const float* cheb_b = (const float*)d_in[6];
    const float* bn_g   = (const float*)d_in[7];
    const float* bn_b   = (const float*)d_in[8];
    const float* w1     = (const float*)d_in[9];
    const float* b1     = (const float*)d_in[10];
    const float* w2     = (const float*)d_in[11];
    const float* b2     = (const float*)d_in[12];
    const int* ei       = (const int*)d_in[13];
    const int* batch    = (const int*)d_in[14];
    float* out = (float*)d_out;

    cudaFuncSetAttribute(k_embed_mma, cudaFuncAttributeMaxDynamicSharedMemorySize, SMEM_DYN);
    cudaFuncSetAttribute(k_cheb_mma,  cudaFuncAttributeMaxDynamicSharedMemorySize, SMEM_DYN);

    const int FV = NN * HH / 4;
    const int FB = FV / 256;                 // 6250
    const int NODE_WARP_BLKS = (NN + 7) / 8; // 6250

    k_init<<<(NN + 255) / 256, 256>>>();
    k_edge_prep<<<EE / 256, 256>>>(ei);
    k_dinv<<<(NN + 255) / 256, 256>>>();
    k_scan1<<<NBLK, SCAN_B>>>();
    k_scan2<<<1, SCAN_B>>>();
    k_scan3<<<NBLK, SCAN_B>>>();
    k_scatter<<<EE / 256, 256>>>();

    k_embed_mma<<<NTILE, 256, SMEM_DYN>>>(x, w_in, b_in, ln_g, ln_b);

    for (int l = 0; l < LL; l++) {
        k_spmm1<<<NODE_WARP_BLKS, 256>>>();
        k_spmm2<<<NODE_WARP_BLKS, 256>>>();
        k_cheb_mma<<<NTILE, 256, SMEM_DYN>>>(cheb_w + (size_t)l * KK * HH * HH,
                                             cheb_b + (size_t)l * HH);
        k_bnfin<<<1, HH>>>(bn_g + (size_t)l * HH, bn_b + (size_t)l * HH);
        k_bnapply<<<FB, 256>>>();
    }

    k_regedge<<<1024, 256>>>();
    k_pool<<<(NN * 32 + 255) / 256, 256>>>(batch);
    k_head<<<GG, HH>>>(w1, b1, w2, b2, out, out_size);
}

// round 6
// speedup vs baseline: 11.6026x; 1.4415x over previous
#include <cuda_runtime.h>
#include <cstdint>

#define NN 50000
#define EE 800000
#define GG 128
#define HH 128
#define LL 3
#define KK 3
#define EPSF 1e-5f
#define SCAN_B 256
#define NBLK ((NN + SCAN_B - 1) / SCAN_B)   // 196
#define NTILE ((NN + 127) / 128)            // 391

// ---------------- scratch (static device globals; no allocation) ----------------
__device__ float g_h [NN*HH];
__device__ float g_t1[NN*HH];
__device__ float g_t2[NN*HH];
__device__ float g_o [NN*HH];
__device__ int   g_src[EE];
__device__ int   g_dst[EE];
__device__ int   g_ecol[EE];
__device__ float g_ew [EE];
__device__ int   g_degi[NN];
__device__ float g_dinv[NN];
__device__ int   g_cnt[NN];
__device__ int   g_incl[NN];
__device__ int   g_bsum[SCAN_B];
__device__ int   g_bscan[SCAN_B];
__device__ int   g_rowptr[NN+1];
__device__ int   g_cur[NN];
__device__ float g_bnsum[HH];
__device__ float g_bnsq [HH];
__device__ float g_bnscale[HH];
__device__ float g_bnshift[HH];
__device__ double g_reg;
__device__ float g_gsum[GG*HH];
__device__ float g_gcnt[GG];

// ================= helpers =================
__device__ __forceinline__ uint32_t smem_u32(const void* p) {
    uint32_t a;
    asm("{ .reg .u64 t; cvta.to.shared.u64 t, %1; cvt.u32.u64 %0, t; }"
        : "=r"(a) : "l"(p));
    return a;
}

// D += A(16x8,row) * B(8x8,col)  tf32 inputs (raw fp32 bits = truncation), f32 accum
__device__ __forceinline__ void mma_tf32(float* d, const uint32_t* a, const uint32_t* b) {
    asm volatile(
        "mma.sync.aligned.m16n8k8.row.col.f32.tf32.tf32.f32 "
        "{%0,%1,%2,%3}, {%4,%5,%6,%7}, {%8,%9}, {%0,%1,%2,%3};"
        : "+f"(d[0]), "+f"(d[1]), "+f"(d[2]), "+f"(d[3])
        : "r"(a[0]), "r"(a[1]), "r"(a[2]), "r"(a[3]), "r"(b[0]), "r"(b[1]));
}

__device__ __forceinline__ void cp16(uint32_t dst, const void* src, bool pred) {
    int sz = pred ? 16 : 0;
    asm volatile("cp.async.cg.shared.global [%0], [%1], 16, %2;"
                 :: "r"(dst), "l"(src), "r"(sz));
}
#define CP_COMMIT() asm volatile("cp.async.commit_group;" ::: "memory")
#define CP_WAIT1()  asm volatile("cp.async.wait_group 1;" ::: "memory")
#define CP_WAIT0()  asm volatile("cp.async.wait_group 0;" ::: "memory")

// smem layout (uint32 units): double-buffered As/Bs; stage overlaps them
#define AS_PITCH 36
#define BS_PITCH 132
#define ST_PITCH 129
#define OFF_AS0  0
#define OFF_AS1  4608
#define OFF_BS0  9216
#define OFF_BS1  13440
#define OFF_STAGE 0
#define OFF_EXTRA 17664
#define SMEM_U32 (OFF_EXTRA + 128*6)
#define SMEM_DYN (SMEM_U32*4)     // 73728+3072 = ~75 KB

// async-load A chunk [128 x 32] floats into As buf
__device__ __forceinline__ void load_A_async(
    uint32_t sbase, int bufoff, const float* __restrict__ src, int row0, int kc)
{
    const float4* s4 = (const float4*)src;
    #pragma unroll
    for (int it = 0; it < 4; it++) {
        int idx = it * 256 + threadIdx.x;
        int r = idx >> 3, c4 = idx & 7;
        const float4* gp = s4 + (size_t)(row0 + r) * 32 + kc * 8 + c4;
        uint32_t dst = sbase + (bufoff + r * AS_PITCH + c4 * 4) * 4;
        cp16(dst, gp, row0 + r < NN);
    }
}

// async-load B chunk [32 x 128] floats into Bs buf
__device__ __forceinline__ void load_B_async(
    uint32_t sbase, int bufoff, const float* __restrict__ W, int kc)
{
    const float4* s4 = (const float4*)W;
    #pragma unroll
    for (int it = 0; it < 4; it++) {
        int idx = it * 256 + threadIdx.x;
        int r = idx >> 5, c4 = idx & 31;
        const float4* gp = s4 + (size_t)(kc * 32 + r) * 32 + c4;
        uint32_t dst = sbase + (bufoff + r * BS_PITCH + c4 * 4) * 4;
        cp16(dst, gp, true);
    }
}

// one 32-wide K chunk of MMAs
__device__ __forceinline__ void mma_chunk(
    const uint32_t* As, const uint32_t* Bs,
    float acc[2][8][4], int m0, int n0, int g, int t)
{
    #pragma unroll
    for (int ks = 0; ks < 4; ks++) {
        int k0 = ks * 8;
        uint32_t a[2][4];
        #pragma unroll
        for (int mf = 0; mf < 2; mf++) {
            int r = m0 + mf * 16 + g;
            a[mf][0] = As[r * AS_PITCH + k0 + t];
            a[mf][1] = As[(r + 8) * AS_PITCH + k0 + t];
            a[mf][2] = As[r * AS_PITCH + k0 + t + 4];
            a[mf][3] = As[(r + 8) * AS_PITCH + k0 + t + 4];
        }
        #pragma unroll
        for (int nf = 0; nf < 8; nf++) {
            int c = n0 + nf * 8 + g;
            uint32_t b[2];
            b[0] = Bs[(k0 + t) * BS_PITCH + c];
            b[1] = Bs[(k0 + t + 4) * BS_PITCH + c];
            mma_tf32(acc[0][nf], a[0], b);
            mma_tf32(acc[1][nf], a[1], b);
        }
    }
}

__device__ __forceinline__ void acc_to_stage(
    float* stage, const float* biasS, float acc[2][8][4],
    int m0, int n0, int g, int t)
{
    #pragma unroll
    for (int mf = 0; mf < 2; mf++) {
        #pragma unroll
        for (int nf = 0; nf < 8; nf++) {
            int c = n0 + nf * 8 + 2 * t;
            int r = m0 + mf * 16 + g;
            stage[r * ST_PITCH + c]           = acc[mf][nf][0] + biasS[c];
            stage[r * ST_PITCH + c + 1]       = acc[mf][nf][1] + biasS[c + 1];
            stage[(r + 8) * ST_PITCH + c]     = acc[mf][nf][2] + biasS[c];
            stage[(r + 8) * ST_PITCH + c + 1] = acc[mf][nf][3] + biasS[c + 1];
        }
    }
}

// ---------------- init ----------------
__global__ void k_init() {
    int i = blockIdx.x * blockDim.x + threadIdx.x;
    if (i < NN)    { g_degi[i] = 0; g_cnt[i] = 0; g_cur[i] = 0; }
    if (i < GG*HH)   g_gsum[i] = 0.f;
    if (i < GG)      g_gcnt[i] = 0.f;
    if (i < HH)    { g_bnsum[i] = 0.f; g_bnsq[i] = 0.f; }
    if (i == 0)      g_reg = 0.0;
}

// ---------------- edge prep ----------------
__global__ void k_edge_prep(const int* __restrict__ ei) {
    int e = blockIdx.x * blockDim.x + threadIdx.x;
    if (e >= EE) return;
    int s = ei[e];
    int d = ei[EE + e];
    g_src[e] = s;
    g_dst[e] = d;
    atomicAdd(&g_degi[s], 1);
    atomicAdd(&g_cnt[d], 1);
}

__global__ void k_dinv() {
    int i = blockIdx.x * blockDim.x + threadIdx.x;
    if (i >= NN) return;
    int d = g_degi[i];
    g_dinv[i] = d > 0 ? rsqrtf((float)d) : 0.f;
}

// ---------------- scan ----------------
__global__ void k_scan1() {
    __shared__ int sm[SCAN_B];
    int i = blockIdx.x * SCAN_B + threadIdx.x;
    int v = (i < NN) ? g_cnt[i] : 0;
    sm[threadIdx.x] = v;
    __syncthreads();
    #pragma unroll
    for (int off = 1; off < SCAN_B; off <<= 1) {
        int t = (threadIdx.x >= off) ? sm[threadIdx.x - off] : 0;
        __syncthreads();
        sm[threadIdx.x] += t;
        __syncthreads();
    }
    if (i < NN) g_incl[i] = sm[threadIdx.x];
    if (threadIdx.x == SCAN_B - 1) g_bsum[blockIdx.x] = sm[threadIdx.x];
}

__global__ void k_scan2() {
    __shared__ int sm[SCAN_B];
    int t0 = threadIdx.x;
    sm[t0] = (t0 < NBLK) ? g_bsum[t0] : 0;
    __syncthreads();
    #pragma unroll
    for (int off = 1; off < SCAN_B; off <<= 1) {
        int t = (t0 >= off) ? sm[t0 - off] : 0;
        __syncthreads();
        sm[t0] += t;
        __syncthreads();
    }
    g_bscan[t0] = sm[t0];
}

__global__ void k_scan3() {
    int i = blockIdx.x * SCAN_B + threadIdx.x;
    if (i < NN) {
        int off = (blockIdx.x > 0) ? g_bscan[blockIdx.x - 1] : 0;
        g_rowptr[i] = g_incl[i] - g_cnt[i] + off;
    }
    if (i == 0) g_rowptr[NN] = EE;
}

__global__ void k_scatter() {
    int e = blockIdx.x * blockDim.x + threadIdx.x;
    if (e >= EE) return;
    int s = g_src[e], d = g_dst[e];
    int pos = g_rowptr[d] + atomicAdd(&g_cur[d], 1);
    g_ecol[pos] = s;
    g_ew[pos] = -g_dinv[s] * g_dinv[d];
}

// ---------------- embed: x@W + b -> LayerNorm -> ReLU  (pipelined tf32 mma) ----------------
__global__ void __launch_bounds__(256) k_embed_mma(
    const float* __restrict__ x, const float* __restrict__ W,
    const float* __restrict__ b_in, const float* __restrict__ lng,
    const float* __restrict__ lnb)
{
    extern __shared__ uint32_t smem[];
    uint32_t sbase = smem_u32(smem);
    float* stage = (float*)(smem + OFF_STAGE);
    float* biasS = (float*)(smem + OFF_EXTRA);
    float* lngS  = biasS + 128;
    float* lnbS  = lngS + 128;
    float* muS   = lnbS + 128;
    float* rsS   = muS + 128;

    int tid = threadIdx.x;
    int lane = tid & 31, warp = tid >> 5;
    int g = lane >> 2, t = lane & 3;
    int m0 = (warp >> 1) * 32, n0 = (warp & 1) * 64;
    int row0 = blockIdx.x * 128;

    if (tid < 128) {
        biasS[tid] = b_in[tid];
        lngS[tid]  = lng[tid];
        lnbS[tid]  = lnb[tid];
    }

    float acc[2][8][4];
    #pragma unroll
    for (int i = 0; i < 2; i++)
        #pragma unroll
        for (int j = 0; j < 8; j++)
            { acc[i][j][0]=0.f; acc[i][j][1]=0.f; acc[i][j][2]=0.f; acc[i][j][3]=0.f; }

    const int NCH = 4;
    load_A_async(sbase, OFF_AS0, x, row0, 0);
    load_B_async(sbase, OFF_BS0, W, 0);
    CP_COMMIT();

    for (int i = 0; i < NCH; i++) {
        int abuf = (i & 1) ? OFF_AS1 : OFF_AS0;
        int bbuf = (i & 1) ? OFF_BS1 : OFF_BS0;
        if (i + 1 < NCH) {
            int a2 = ((i + 1) & 1) ? OFF_AS1 : OFF_AS0;
            int b2 = ((i + 1) & 1) ? OFF_BS1 : OFF_BS0;
            load_A_async(sbase, a2, x, row0, i + 1);
            load_B_async(sbase, b2, W, i + 1);
            CP_COMMIT();
            CP_WAIT1();
        } else {
            CP_WAIT0();
        }
        __syncthreads();
        mma_chunk(smem + abuf, smem + bbuf, acc, m0, n0, g, t);
        __syncthreads();
    }

    acc_to_stage(stage, biasS, acc, m0, n0, g, t);
    __syncthreads();

    if (tid < 128) {
        float s = 0.f, sq = 0.f;
        #pragma unroll 8
        for (int c = 0; c < HH; c++) {
            float v = stage[tid * ST_PITCH + c];
            s += v; sq = fmaf(v, v, sq);
        }
        float mu  = s * (1.f / HH);
        float var = sq * (1.f / HH) - mu * mu;
        muS[tid] = mu;
        rsS[tid] = rsqrtf(var + EPSF);
    }
    __syncthreads();

    for (int idx = tid; idx < 128 * HH; idx += 256) {
        int r = idx >> 7, c = idx & 127;
        if (row0 + r < NN) {
            float v = stage[r * ST_PITCH + c];
            v = (v - muS[r]) * rsS[r] * lngS[c] + lnbS[c];
            g_h[(size_t)(row0 + r) * HH + c] = fmaxf(v, 0.f);
        }
    }
}

// ---------------- cheb: g_o = h@W0 + t1@W1 + t2@W2 + b; fused BN stats ----------------
__global__ void __launch_bounds__(256) k_cheb_mma(
    const float* __restrict__ W, const float* __restrict__ bias)
{
    extern __shared__ uint32_t smem[];
    uint32_t sbase = smem_u32(smem);
    float* stage = (float*)(smem + OFF_STAGE);
    float* biasS = (float*)(smem + OFF_EXTRA);
    float* sCs   = biasS + 128;
    float* sCq   = sCs + 128;

    int tid = threadIdx.x;
    int lane = tid & 31, warp = tid >> 5;
    int g = lane >> 2, t = lane & 3;
    int m0 = (warp >> 1) * 32, n0 = (warp & 1) * 64;
    int row0 = blockIdx.x * 128;

    if (tid < 128) { biasS[tid] = bias[tid]; sCs[tid] = 0.f; sCq[tid] = 0.f; }

    float acc[2][8][4];
    #pragma unroll
    for (int i = 0; i < 2; i++)
        #pragma unroll
        for (int j = 0; j < 8; j++)
            { acc[i][j][0]=0.f; acc[i][j][1]=0.f; acc[i][j][2]=0.f; acc[i][j][3]=0.f; }

    const float* Asrc[3] = { g_h, g_t1, g_t2 };
    const int NCH = 12;
    load_A_async(sbase, OFF_AS0, Asrc[0], row0, 0);
    load_B_async(sbase, OFF_BS0, W, 0);
    CP_COMMIT();

    for (int i = 0; i < NCH; i++) {
        int abuf = (i & 1) ? OFF_AS1 : OFF_AS0;
        int bbuf = (i & 1) ? OFF_BS1 : OFF_BS0;
        if (i + 1 < NCH) {
            int j = i + 1;
            int a2 = (j & 1) ? OFF_AS1 : OFF_AS0;
            int b2 = (j & 1) ? OFF_BS1 : OFF_BS0;
            load_A_async(sbase, a2, Asrc[j >> 2], row0, j & 3);
            load_B_async(sbase, b2, W + (size_t)(j >> 2) * HH * HH, j & 3);
            CP_COMMIT();
            CP_WAIT1();
        } else {
            CP_WAIT0();
        }
        __syncthreads();
        mma_chunk(smem + abuf, smem + bbuf, acc, m0, n0, g, t);
        __syncthreads();
    }

    acc_to_stage(stage, biasS, acc, m0, n0, g, t);
    __syncthreads();

    // store + per-column BN partials (each thread owns column c = tid & 127)
    {
        float ps = 0.f, pq = 0.f;
        int c = tid & 127;
        int rbase = tid >> 7;
        #pragma unroll 4
        for (int k = 0; k < 64; k++) {
            int r = rbase + k * 2;
            int row = row0 + r;
            if (row < NN) {
                float v = stage[r * ST_PITCH + c];
                g_o[(size_t)row * HH + c] = v;
                ps += v; pq = fmaf(v, v, pq);
            }
        }
        atomicAdd(&sCs[c], ps);
        atomicAdd(&sCq[c], pq);
    }
    __syncthreads();
    if (tid < 128) {
        atomicAdd(&g_bnsum[tid], sCs[tid]);
        atomicAdd(&g_bnsq[tid],  sCq[tid]);
    }
}

// ---------------- CSR spmm #1: t1 = L_hat h; fused Dirichlet reg (x4 unrolled) ----------------
__global__ void __launch_bounds__(256) k_spmm1() {
    __shared__ float blk_ss[8];
    int warp = blockIdx.x * 8 + (threadIdx.x >> 5);
    int lane = threadIdx.x & 31;
    float ss = 0.f;
    if (warp < NN) {
        int beg = g_rowptr[warp], end = g_rowptr[warp + 1];
        float4 hd = ((const float4*)g_h)[(size_t)warp * 32 + lane];
        float4 acc = make_float4(0.f, 0.f, 0.f, 0.f);
        int e = beg;
        for (; e + 4 <= end; e += 4) {
            int s0 = g_ecol[e],   s1 = g_ecol[e+1];
            int s2 = g_ecol[e+2], s3 = g_ecol[e+3];
            float w0 = g_ew[e],   w1 = g_ew[e+1];
            float w2 = g_ew[e+2], w3 = g_ew[e+3];
            float4 h0 = ((const float4*)g_h)[(size_t)s0 * 32 + lane];
            float4 h1 = ((const float4*)g_h)[(size_t)s1 * 32 + lane];
            float4 h2 = ((const float4*)g_h)[(size_t)s2 * 32 + lane];
            float4 h3 = ((const float4*)g_h)[(size_t)s3 * 32 + lane];
            acc.x = fmaf(w0,h0.x,acc.x); acc.y = fmaf(w0,h0.y,acc.y);
            acc.z = fmaf(w0,h0.z,acc.z); acc.w = fmaf(w0,h0.w,acc.w);
            float d0x=h0.x-hd.x, d0y=h0.y-hd.y, d0z=h0.z-hd.z, d0w=h0.w-hd.w;
            ss=fmaf(d0x,d0x,ss); ss=fmaf(d0y,d0y,ss); ss=fmaf(d0z,d0z,ss); ss=fmaf(d0w,d0w,ss);
            acc.x = fmaf(w1,h1.x,acc.x); acc.y = fmaf(w1,h1.y,acc.y);
            acc.z = fmaf(w1,h1.z,acc.z); acc.w = fmaf(w1,h1.w,acc.w);
            float d1x=h1.x-hd.x, d1y=h1.y-hd.y, d1z=h1.z-hd.z, d1w=h1.w-hd.w;
            ss=fmaf(d1x,d1x,ss); ss=fmaf(d1y,d1y,ss); ss=fmaf(d1z,d1z,ss); ss=fmaf(d1w,d1w,ss);
            acc.x = fmaf(w2,h2.x,acc.x); acc.y = fmaf(w2,h2.y,acc.y);
            acc.z = fmaf(w2,h2.z,acc.z); acc.w = fmaf(w2,h2.w,acc.w);
            float d2x=h2.x-hd.x, d2y=h2.y-hd.y, d2z=h2.z-hd.z, d2w=h2.w-hd.w;
            ss=fmaf(d2x,d2x,ss); ss=fmaf(d2y,d2y,ss); ss=fmaf(d2z,d2z,ss); ss=fmaf(d2w,d2w,ss);
            acc.x = fmaf(w3,h3.x,acc.x); acc.y = fmaf(w3,h3.y,acc.y);
            acc.z = fmaf(w3,h3.z,acc.z); acc.w = fmaf(w3,h3.w,acc.w);
            float d3x=h3.x-hd.x, d3y=h3.y-hd.y, d3z=h3.z-hd.z, d3w=h3.w-hd.w;
            ss=fmaf(d3x,d3x,ss); ss=fmaf(d3y,d3y,ss); ss=fmaf(d3z,d3z,ss); ss=fmaf(d3w,d3w,ss);
        }
        for (; e < end; e++) {
            int s = g_ecol[e];
            float w = g_ew[e];
            float4 hv = ((const float4*)g_h)[(size_t)s * 32 + lane];
            acc.x = fmaf(w,hv.x,acc.x); acc.y = fmaf(w,hv.y,acc.y);
            acc.z = fmaf(w,hv.z,acc.z); acc.w = fmaf(w,hv.w,acc.w);
            float dx=hv.x-hd.x, dy=hv.y-hd.y, dz=hv.z-hd.z, dw=hv.w-hd.w;
            ss=fmaf(dx,dx,ss); ss=fmaf(dy,dy,ss); ss=fmaf(dz,dz,ss); ss=fmaf(dw,dw,ss);
        }
        ((float4*)g_t1)[(size_t)warp * 32 + lane] = acc;
    }
    #pragma unroll
    for (int off = 16; off > 0; off >>= 1)
        ss += __shfl_xor_sync(0xffffffffu, ss, off);
    if (lane == 0) blk_ss[threadIdx.x >> 5] = ss;
    __syncthreads();
    if (threadIdx.x == 0) {
        double tot = 0.0;
        #pragma unroll
        for (int j = 0; j < 8; j++) tot += (double)blk_ss[j];
        atomicAdd(&g_reg, tot);
    }
}

// ---------------- CSR spmm #2: t2 = 2 L_hat t1 - h  (x4 unrolled) ----------------
__global__ void __launch_bounds__(256) k_spmm2() {
    int warp = blockIdx.x * 8 + (threadIdx.x >> 5);
    if (warp >= NN) return;
    int lane = threadIdx.x & 31;
    int beg = g_rowptr[warp], end = g_rowptr[warp + 1];
    float4 acc = make_float4(0.f, 0.f, 0.f, 0.f);
    int e = beg;
    for (; e + 4 <= end; e += 4) {
        int s0 = g_ecol[e],   s1 = g_ecol[e+1];
        int s2 = g_ecol[e+2], s3 = g_ecol[e+3];
        float w0 = g_ew[e],   w1 = g_ew[e+1];
        float w2 = g_ew[e+2], w3 = g_ew[e+3];
        float4 h0 = ((const float4*)g_t1)[(size_t)s0 * 32 + lane];
        float4 h1 = ((const float4*)g_t1)[(size_t)s1 * 32 + lane];
        float4 h2 = ((const float4*)g_t1)[(size_t)s2 * 32 + lane];
        float4 h3 = ((const float4*)g_t1)[(size_t)s3 * 32 + lane];
        acc.x = fmaf(w0,h0.x,acc.x); acc.y = fmaf(w0,h0.y,acc.y);
        acc.z = fmaf(w0,h0.z,acc.z); acc.w = fmaf(w0,h0.w,acc.w);
        acc.x = fmaf(w1,h1.x,acc.x); acc.y = fmaf(w1,h1.y,acc.y);
        acc.z = fmaf(w1,h1.z,acc.z); acc.w = fmaf(w1,h1.w,acc.w);
        acc.x = fmaf(w2,h2.x,acc.x); acc.y = fmaf(w2,h2.y,acc.y);
        acc.z = fmaf(w2,h2.z,acc.z); acc.w = fmaf(w2,h2.w,acc.w);
        acc.x = fmaf(w3,h3.x,acc.x); acc.y = fmaf(w3,h3.y,acc.y);
        acc.z = fmaf(w3,h3.z,acc.z); acc.w = fmaf(w3,h3.w,acc.w);
    }
    for (; e < end; e++) {
        int s = g_ecol[e];
        float w = g_ew[e];
        float4 hv = ((const float4*)g_t1)[(size_t)s * 32 + lane];
        acc.x = fmaf(w,hv.x,acc.x); acc.y = fmaf(w,hv.y,acc.y);
        acc.z = fmaf(w,hv.z,acc.z); acc.w = fmaf(w,hv.w,acc.w);
    }
    float4 hd = ((const float4*)g_h)[(size_t)warp * 32 + lane];
    float4 o;
    o.x = 2.f * acc.x - hd.x;
    o.y = 2.f * acc.y - hd.y;
    o.z = 2.f * acc.z - hd.z;
    o.w = 2.f * acc.w - hd.w;
    ((float4*)g_t2)[(size_t)warp * 32 + lane] = o;
}

// ---------------- reg-only pass via CSR (dst row loaded once per node) ----------------
__global__ void __launch_bounds__(256) k_regedge() {
    __shared__ float blk_ss[8];
    int warp = blockIdx.x * 8 + (threadIdx.x >> 5);
    int lane = threadIdx.x & 31;
    float ss = 0.f;
    if (warp < NN) {
        int beg = g_rowptr[warp], end = g_rowptr[warp + 1];
        float4 hd = ((const float4*)g_h)[(size_t)warp * 32 + lane];
        int e = beg;
        for (; e + 4 <= end; e += 4) {
            int s0 = g_ecol[e],   s1 = g_ecol[e+1];
            int s2 = g_ecol[e+2], s3 = g_ecol[e+3];
            float4 h0 = ((const float4*)g_h)[(size_t)s0 * 32 + lane];
            float4 h1 = ((const float4*)g_h)[(size_t)s1 * 32 + lane];
            float4 h2 = ((const float4*)g_h)[(size_t)s2 * 32 + lane];
            float4 h3 = ((const float4*)g_h)[(size_t)s3 * 32 + lane];
            float dx, dy, dz, dw;
            dx=h0.x-hd.x; dy=h0.y-hd.y; dz=h0.z-hd.z; dw=h0.w-hd.w;
            ss=fmaf(dx,dx,ss); ss=fmaf(dy,dy,ss); ss=fmaf(dz,dz,ss); ss=fmaf(dw,dw,ss);
            dx=h1.x-hd.x; dy=h1.y-hd.y; dz=h1.z-hd.z; dw=h1.w-hd.w;
            ss=fmaf(dx,dx,ss); ss=fmaf(dy,dy,ss); ss=fmaf(dz,dz,ss); ss=fmaf(dw,dw,ss);
            dx=h2.x-hd.x; dy=h2.y-hd.y; dz=h2.z-hd.z; dw=h2.w-hd.w;
            ss=fmaf(dx,dx,ss); ss=fmaf(dy,dy,ss); ss=fmaf(dz,dz,ss); ss=fmaf(dw,dw,ss);
            dx=h3.x-hd.x; dy=h3.y-hd.y; dz=h3.z-hd.z; dw=h3.w-hd.w;
            ss=fmaf(dx,dx,ss); ss=fmaf(dy,dy,ss); ss=fmaf(dz,dz,ss); ss=fmaf(dw,dw,ss);
        }
        for (; e < end; e++) {
            int s = g_ecol[e];
            float4 hv = ((const float4*)g_h)[(size_t)s * 32 + lane];
            float dx=hv.x-hd.x, dy=hv.y-hd.y, dz=hv.z-hd.z, dw=hv.w-hd.w;
            ss=fmaf(dx,dx,ss); ss=fmaf(dy,dy,ss); ss=fmaf(dz,dz,ss); ss=fmaf(dw,dw,ss);
        }
    }
    #pragma unroll
    for (int off = 16; off > 0; off >>= 1)
        ss += __shfl_xor_sync(0xffffffffu, ss, off);
    if (lane == 0) blk_ss[threadIdx.x >> 5] = ss;
    __syncthreads();
    if (threadIdx.x == 0) {
        double tot = 0.0;
        #pragma unroll
        for (int j = 0; j < 8; j++) tot += (double)blk_ss[j];
        atomicAdd(&g_reg, tot);
    }
}

// ---------------- BN finalize + apply ----------------
__global__ void k_bnfin(const float* __restrict__ bng, const float* __restrict__ bnb) {
    int c = threadIdx.x;
    float m = g_bnsum[c] * (1.f / NN);
    float v = g_bnsq[c] * (1.f / NN) - m * m;
    float sc = bng[c] * rsqrtf(v + EPSF);
    g_bnscale[c] = sc;
    g_bnshift[c] = bnb[c] - m * sc;
    g_bnsum[c] = 0.f;
    g_bnsq[c]  = 0.f;
}

__global__ void k_bnapply() {
    int i = blockIdx.x * blockDim.x + threadIdx.x;
    int c4 = i & 31;
    float4 v  = ((const float4*)g_o)[i];
    float4 sc = ((const float4*)g_bnscale)[c4];
    float4 sh = ((const float4*)g_bnshift)[c4];
    float4 o;
    o.x = fmaxf(fmaf(v.x, sc.x, sh.x), 0.f);
    o.y = fmaxf(fmaf(v.y, sc.y, sh.y), 0.f);
    o.z = fmaxf(fmaf(v.z, sc.z, sh.z), 0.f);
    o.w = fmaxf(fmaf(v.w, sc.w, sh.w), 0.f);
    ((float4*)g_h)[i] = o;
}

// ---------------- global mean pool ----------------
__global__ void __launch_bounds__(256) k_pool(const int* __restrict__ batch) {
    int warp = (blockIdx.x * 256 + threadIdx.x) >> 5;
    if (warp >= NN) return;
    int lane = threadIdx.x & 31;
    int b = batch[warp];
    float4 hv = ((const float4*)g_h)[(size_t)warp * 32 + lane];
    float* gp = &g_gsum[(size_t)b * HH + lane * 4];
    atomicAdd(gp + 0, hv.x);
    atomicAdd(gp + 1, hv.y);
    atomicAdd(gp + 2, hv.z);
    atomicAdd(gp + 3, hv.w);
    if (lane == 0) atomicAdd(&g_gcnt[b], 1.f);
}

// ---------------- MLP head + output ----------------
__global__ void k_head(const float* __restrict__ w1, const float* __restrict__ b1,
                       const float* __restrict__ w2, const float* __restrict__ b2,
                       float* __restrict__ out, int out_size)
{
    __shared__ float gm[HH];
    __shared__ float zz[64];
    int g = blockIdx.x, t = threadIdx.x;
    float cnt = fmaxf(g_gcnt[g], 1.f);
    gm[t] = g_gsum[(size_t)g * HH + t] / cnt;
    __syncthreads();
    if (t < 64) {
        float a = b1[t];
        #pragma unroll 4
        for (int c = 0; c < HH; c++) a = fmaf(gm[c], w1[c * 64 + t], a);
        zz[t] = fmaxf(a, 0.f);
    }
    __syncthreads();
    if (t < 2) {
        float a = b2[t];
        #pragma unroll 4
        for (int k = 0; k < 64; k++) a = fmaf(zz[k], w2[k * 2 + t], a);
        out[g * 2 + t] = a;
    }
    if (g == 0 && t == 0 && out_size > 256)
        out[256] = (float)(g_reg / (4.0 * (double)EE));
}

// ---------------- launch ----------------
extern "C" void kernel_launch(void* const* d_in, const int* in_sizes, int n_in,
                              void* d_out, int out_size)
{
    const float* x      = (const float*)d_in[0];
    const float* w_in   = (const float*)d_in[1];
    const float* b_in   = (const float*)d_in[2];
    const float* ln_g   = (const float*)d_in[3];
    const float* ln_b   = (const float*)d_in[4];
    const float* cheb_w = (const float*)d_in[5];
    const float* cheb_b = (const float*)d_in[6];
    const float* bn_g   = (const float*)d_in[7];
    const float* bn_b   = (const float*)d_in[8];
    const float* w1     = (const float*)d_in[9];
    const float* b1     = (const float*)d_in[10];
    const float* w2     = (const float*)d_in[11];
    const float* b2     = (const float*)d_in[12];
    const int* ei       = (const int*)d_in[13];
    const int* batch    = (const int*)d_in[14];
    float* out = (float*)d_out;

    cudaFuncSetAttribute(k_embed_mma, cudaFuncAttributeMaxDynamicSharedMemorySize, SMEM_DYN);
    cudaFuncSetAttribute(k_cheb_mma,  cudaFuncAttributeMaxDynamicSharedMemorySize, SMEM_DYN);

    const int FV = NN * HH / 4;
    const int FB = FV / 256;                 // 6250
    const int NODE_WARP_BLKS = (NN + 7) / 8; // 6250

    k_init<<<(NN + 255) / 256, 256>>>();
    k_edge_prep<<<EE / 256, 256>>>(ei);
    k_dinv<<<(NN + 255) / 256, 256>>>();
    k_scan1<<<NBLK, SCAN_B>>>();
    k_scan2<<<1, SCAN_B>>>();
    k_scan3<<<NBLK, SCAN_B>>>();
    k_scatter<<<EE / 256, 256>>>();

    k_embed_mma<<<NTILE, 256, SMEM_DYN>>>(x, w_in, b_in, ln_g, ln_b);

    for (int l = 0; l < LL; l++) {
        k_spmm1<<<NODE_WARP_BLKS, 256>>>();
        k_spmm2<<<NODE_WARP_BLKS, 256>>>();
        k_cheb_mma<<<NTILE, 256, SMEM_DYN>>>(cheb_w + (size_t)l * KK * HH * HH,
                                             cheb_b + (size_t)l * HH);
        k_bnfin<<<1, HH>>>(bn_g + (size_t)l * HH, bn_b + (size_t)l * HH);
        k_bnapply<<<FB, 256>>>();
    }

    k_regedge<<<NODE_WARP_BLKS, 256>>>();
    k_pool<<<(NN * 32 + 255) / 256, 256>>>(batch);
    k_head<<<GG, HH>>>(w1, b1, w2, b2, out, out_size);
}

// round 7
// speedup vs baseline: 12.1449x; 1.0467x over previous
#include <cuda_runtime.h>
#include <cuda_fp16.h>
#include <cstdint>

#define NN 50000
#define EE 800000
#define GG 128
#define HH 128
#define LL 3
#define KK 3
#define EPSF 1e-5f
#define SCAN_B 256
#define NBLK ((NN + SCAN_B - 1) / SCAN_B)   // 196
#define NTILE ((NN + 127) / 128)            // 391

// ---------------- scratch (static device globals; no allocation) ----------------
__device__ __half g_h [NN*HH];
__device__ __half g_t1[NN*HH];
__device__ __half g_t2[NN*HH];
__device__ __half g_o [NN*HH];
__device__ int   g_src[EE];
__device__ int   g_dst[EE];
__device__ int   g_ecol[EE];
__device__ float g_ew [EE];
__device__ int   g_degi[NN];
__device__ float g_dinv[NN];
__device__ int   g_cnt[NN];
__device__ int   g_incl[NN];
__device__ int   g_bsum[SCAN_B];
__device__ int   g_bscan[SCAN_B];
__device__ int   g_rowptr[NN+1];
__device__ int   g_cur[NN];
__device__ float g_bnsum[HH];
__device__ float g_bnsq [HH];
__device__ float g_bnscale[HH];
__device__ float g_bnshift[HH];
__device__ double g_reg;
__device__ float g_gsum[GG*HH];
__device__ float g_gcnt[GG];

// ================= helpers =================
__device__ __forceinline__ uint32_t smem_u32(const void* p) {
    uint32_t a;
    asm("{ .reg .u64 t; cvta.to.shared.u64 t, %1; cvt.u32.u64 %0, t; }"
        : "=r"(a) : "l"(p));
    return a;
}

__device__ __forceinline__ float4 h2f4(uint2 u) {
    __half2 a = *(__half2*)&u.x, b = *(__half2*)&u.y;
    float2 fa = __half22float2(a), fb = __half22float2(b);
    return make_float4(fa.x, fa.y, fb.x, fb.y);
}
__device__ __forceinline__ uint2 f2h4(float4 v) {
    __half2 a = __floats2half2_rn(v.x, v.y);
    __half2 b = __floats2half2_rn(v.z, v.w);
    uint2 u;
    u.x = *(uint32_t*)&a;
    u.y = *(uint32_t*)&b;
    return u;
}

// D += A(16x8,row) * B(8x8,col)  tf32 inputs (raw fp32 bits), f32 accum
__device__ __forceinline__ void mma_tf32(float* d, const uint32_t* a, const uint32_t* b) {
    asm volatile(
        "mma.sync.aligned.m16n8k8.row.col.f32.tf32.tf32.f32 "
        "{%0,%1,%2,%3}, {%4,%5,%6,%7}, {%8,%9}, {%0,%1,%2,%3};"
        : "+f"(d[0]), "+f"(d[1]), "+f"(d[2]), "+f"(d[3])
        : "r"(a[0]), "r"(a[1]), "r"(a[2]), "r"(a[3]), "r"(b[0]), "r"(b[1]));
}

__device__ __forceinline__ void cp16(uint32_t dst, const void* src, bool pred) {
    int sz = pred ? 16 : 0;
    asm volatile("cp.async.cg.shared.global [%0], [%1], 16, %2;"
                 :: "r"(dst), "l"(src), "r"(sz));
}
#define CP_COMMIT() asm volatile("cp.async.commit_group;" ::: "memory")
#define CP_WAIT1()  asm volatile("cp.async.wait_group 1;" ::: "memory")
#define CP_WAIT0()  asm volatile("cp.async.wait_group 0;" ::: "memory")

// smem layout (uint32 units): double-buffered As/Bs; stage overlaps them
#define AS_PITCH 36
#define BS_PITCH 132
#define ST_PITCH 129
#define OFF_AS0  0
#define OFF_AS1  4608
#define OFF_BS0  9216
#define OFF_BS1  13440
#define OFF_STAGE 0
#define OFF_EXTRA 17664
#define SMEM_U32 (OFF_EXTRA + 128*6)
#define SMEM_DYN (SMEM_U32*4)

// async-load fp32 A chunk [128 x 32] into As buf (embed only; x is fp32)
__device__ __forceinline__ void load_A_async(
    uint32_t sbase, int bufoff, const float* __restrict__ src, int row0, int kc)
{
    const float4* s4 = (const float4*)src;
    #pragma unroll
    for (int it = 0; it < 4; it++) {
        int idx = it * 256 + threadIdx.x;
        int r = idx >> 3, c4 = idx & 7;
        const float4* gp = s4 + (size_t)(row0 + r) * 32 + kc * 8 + c4;
        uint32_t dst = sbase + (bufoff + r * AS_PITCH + c4 * 4) * 4;
        cp16(dst, gp, row0 + r < NN);
    }
}

// async-load fp32 B chunk [32 k x 128 n] into Bs buf
__device__ __forceinline__ void load_B_async(
    uint32_t sbase, int bufoff, const float* __restrict__ W, int kc)
{
    const float4* s4 = (const float4*)W;
    #pragma unroll
    for (int it = 0; it < 4; it++) {
        int idx = it * 256 + threadIdx.x;
        int r = idx >> 5, c4 = idx & 31;
        const float4* gp = s4 + (size_t)(kc * 32 + r) * 32 + c4;
        uint32_t dst = sbase + (bufoff + r * BS_PITCH + c4 * 4) * 4;
        cp16(dst, gp, true);
    }
}

// fp16 A chunk: LDG into regs (2 x uint4 = 16 halves per thread)
__device__ __forceinline__ void ldg_A16(
    uint4* r, const __half* __restrict__ src, int row0, int kc)
{
    #pragma unroll
    for (int it = 0; it < 2; it++) {
        int idx = it * 256 + threadIdx.x;
        int rr = idx >> 2, c8 = idx & 3;
        if (row0 + rr < NN)
            r[it] = ((const uint4*)src)[(size_t)(row0 + rr) * 16 + kc * 4 + c8];
        else
            r[it] = make_uint4(0u, 0u, 0u, 0u);
    }
}

// convert regs -> fp32 bits into As buf
__device__ __forceinline__ void sts_A16(uint32_t* As, const uint4* r)
{
    #pragma unroll
    for (int it = 0; it < 2; it++) {
        int idx = it * 256 + threadIdx.x;
        int rr = idx >> 2, c8 = idx & 3;
        uint32_t* p = As + rr * AS_PITCH + c8 * 8;
        const uint32_t* w = (const uint32_t*)&r[it];
        #pragma unroll
        for (int j = 0; j < 4; j++) {
            __half2 h = *(__half2*)&w[j];
            float2 f = __half22float2(h);
            p[j * 2 + 0] = __float_as_uint(f.x);
            p[j * 2 + 1] = __float_as_uint(f.y);
        }
    }
}

// one 32-wide K chunk of MMAs
__device__ __forceinline__ void mma_chunk(
    const uint32_t* As, const uint32_t* Bs,
    float acc[2][8][4], int m0, int n0, int g, int t)
{
    #pragma unroll
    for (int ks = 0; ks < 4; ks++) {
        int k0 = ks * 8;
        uint32_t a[2][4];
        #pragma unroll
        for (int mf = 0; mf < 2; mf++) {
            int r = m0 + mf * 16 + g;
            a[mf][0] = As[r * AS_PITCH + k0 + t];
            a[mf][1] = As[(r + 8) * AS_PITCH + k0 + t];
            a[mf][2] = As[r * AS_PITCH + k0 + t + 4];
            a[mf][3] = As[(r + 8) * AS_PITCH + k0 + t + 4];
        }
        #pragma unroll
        for (int nf = 0; nf < 8; nf++) {
            int c = n0 + nf * 8 + g;
            uint32_t b[2];
            b[0] = Bs[(k0 + t) * BS_PITCH + c];
            b[1] = Bs[(k0 + t + 4) * BS_PITCH + c];
            mma_tf32(acc[0][nf], a[0], b);
            mma_tf32(acc[1][nf], a[1], b);
        }
    }
}

__device__ __forceinline__ void acc_to_stage(
    float* stage, const float* biasS, float acc[2][8][4],
    int m0, int n0, int g, int t)
{
    #pragma unroll
    for (int mf = 0; mf < 2; mf++) {
        #pragma unroll
        for (int nf = 0; nf < 8; nf++) {
            int c = n0 + nf * 8 + 2 * t;
            int r = m0 + mf * 16 + g;
            stage[r * ST_PITCH + c]           = acc[mf][nf][0] + biasS[c];
            stage[r * ST_PITCH + c + 1]       = acc[mf][nf][1] + biasS[c + 1];
            stage[(r + 8) * ST_PITCH + c]     = acc[mf][nf][2] + biasS[c];
            stage[(r + 8) * ST_PITCH + c + 1] = acc[mf][nf][3] + biasS[c + 1];
        }
    }
}

// ---------------- init ----------------
__global__ void k_init() {
    int i = blockIdx.x * blockDim.x + threadIdx.x;
    if (i < NN)    { g_degi[i] = 0; g_cnt[i] = 0; g_cur[i] = 0; }
    if (i < GG*HH)   g_gsum[i] = 0.f;
    if (i < GG)      g_gcnt[i] = 0.f;
    if (i < HH)    { g_bnsum[i] = 0.f; g_bnsq[i] = 0.f; }
    if (i == 0)      g_reg = 0.0;
}

// ---------------- edge prep ----------------
__global__ void k_edge_prep(const int* __restrict__ ei) {
    int e = blockIdx.x * blockDim.x + threadIdx.x;
    if (e >= EE) return;
    int s = ei[e];
    int d = ei[EE + e];
    g_src[e] = s;
    g_dst[e] = d;
    atomicAdd(&g_degi[s], 1);
    atomicAdd(&g_cnt[d], 1);
}

__global__ void k_dinv() {
    int i = blockIdx.x * blockDim.x + threadIdx.x;
    if (i >= NN) return;
    int d = g_degi[i];
    g_dinv[i] = d > 0 ? rsqrtf((float)d) : 0.f;
}

// ---------------- scan ----------------
__global__ void k_scan1() {
    __shared__ int sm[SCAN_B];
    int i = blockIdx.x * SCAN_B + threadIdx.x;
    int v = (i < NN) ? g_cnt[i] : 0;
    sm[threadIdx.x] = v;
    __syncthreads();
    #pragma unroll
    for (int off = 1; off < SCAN_B; off <<= 1) {
        int t = (threadIdx.x >= off) ? sm[threadIdx.x - off] : 0;
        __syncthreads();
        sm[threadIdx.x] += t;
        __syncthreads();
    }
    if (i < NN) g_incl[i] = sm[threadIdx.x];
    if (threadIdx.x == SCAN_B - 1) g_bsum[blockIdx.x] = sm[threadIdx.x];
}

__global__ void k_scan2() {
    __shared__ int sm[SCAN_B];
    int t0 = threadIdx.x;
    sm[t0] = (t0 < NBLK) ? g_bsum[t0] : 0;
    __syncthreads();
    #pragma unroll
    for (int off = 1; off < SCAN_B; off <<= 1) {
        int t = (t0 >= off) ? sm[t0 - off] : 0;
        __syncthreads();
        sm[t0] += t;
        __syncthreads();
    }
    g_bscan[t0] = sm[t0];
}

__global__ void k_scan3() {
    int i = blockIdx.x * SCAN_B + threadIdx.x;
    if (i < NN) {
        int off = (blockIdx.x > 0) ? g_bscan[blockIdx.x - 1] : 0;
        g_rowptr[i] = g_incl[i] - g_cnt[i] + off;
    }
    if (i == 0) g_rowptr[NN] = EE;
}

__global__ void k_scatter() {
    int e = blockIdx.x * blockDim.x + threadIdx.x;
    if (e >= EE) return;
    int s = g_src[e], d = g_dst[e];
    int pos = g_rowptr[d] + atomicAdd(&g_cur[d], 1);
    g_ecol[pos] = s;
    g_ew[pos] = -g_dinv[s] * g_dinv[d];
}

// ---------------- embed: x@W + b -> LayerNorm -> ReLU  (pipelined tf32 mma) ----------------
__global__ void __launch_bounds__(256) k_embed_mma(
    const float* __restrict__ x, const float* __restrict__ W,
    const float* __restrict__ b_in, const float* __restrict__ lng,
    const float* __restrict__ lnb)
{
    extern __shared__ uint32_t smem[];
    uint32_t sbase = smem_u32(smem);
    float* stage = (float*)(smem + OFF_STAGE);
    float* biasS = (float*)(smem + OFF_EXTRA);
    float* lngS  = biasS + 128;
    float* lnbS  = lngS + 128;
    float* muS   = lnbS + 128;
    float* rsS   = muS + 128;

    int tid = threadIdx.x;
    int lane = tid & 31, warp = tid >> 5;
    int g = lane >> 2, t = lane & 3;
    int m0 = (warp >> 1) * 32, n0 = (warp & 1) * 64;
    int row0 = blockIdx.x * 128;

    if (tid < 128) {
        biasS[tid] = b_in[tid];
        lngS[tid]  = lng[tid];
        lnbS[tid]  = lnb[tid];
    }

    float acc[2][8][4];
    #pragma unroll
    for (int i = 0; i < 2; i++)
        #pragma unroll
        for (int j = 0; j < 8; j++)
            { acc[i][j][0]=0.f; acc[i][j][1]=0.f; acc[i][j][2]=0.f; acc[i][j][3]=0.f; }

    const int NCH = 4;
    load_A_async(sbase, OFF_AS0, x, row0, 0);
    load_B_async(sbase, OFF_BS0, W, 0);
    CP_COMMIT();

    for (int i = 0; i < NCH; i++) {
        int abuf = (i & 1) ? OFF_AS1 : OFF_AS0;
        int bbuf = (i & 1) ? OFF_BS1 : OFF_BS0;
        if (i + 1 < NCH) {
            int a2 = ((i + 1) & 1) ? OFF_AS1 : OFF_AS0;
            int b2 = ((i + 1) & 1) ? OFF_BS1 : OFF_BS0;
            load_A_async(sbase, a2, x, row0, i + 1);
            load_B_async(sbase, b2, W, i + 1);
            CP_COMMIT();
            CP_WAIT1();
        } else {
            CP_WAIT0();
        }
        __syncthreads();
        mma_chunk(smem + abuf, smem + bbuf, acc, m0, n0, g, t);
        __syncthreads();
    }

    acc_to_stage(stage, biasS, acc, m0, n0, g, t);
    __syncthreads();

    if (tid < 128) {
        float s = 0.f, sq = 0.f;
        #pragma unroll 8
        for (int c = 0; c < HH; c++) {
            float v = stage[tid * ST_PITCH + c];
            s += v; sq = fmaf(v, v, sq);
        }
        float mu  = s * (1.f / HH);
        float var = sq * (1.f / HH) - mu * mu;
        muS[tid] = mu;
        rsS[tid] = rsqrtf(var + EPSF);
    }
    __syncthreads();

    for (int idx = tid; idx < 128 * HH; idx += 256) {
        int r = idx >> 7, c = idx & 127;
        if (row0 + r < NN) {
            float v = stage[r * ST_PITCH + c];
            v = (v - muS[r]) * rsS[r] * lngS[c] + lnbS[c];
            g_h[(size_t)(row0 + r) * HH + c] = __float2half(fmaxf(v, 0.f));
        }
    }
}

// ---------------- cheb: g_o = h@W0 + t1@W1 + t2@W2 + b; fused BN stats ----------------
__global__ void __launch_bounds__(256) k_cheb_mma(
    const float* __restrict__ W, const float* __restrict__ bias)
{
    extern __shared__ uint32_t smem[];
    uint32_t sbase = smem_u32(smem);
    float* stage = (float*)(smem + OFF_STAGE);
    float* biasS = (float*)(smem + OFF_EXTRA);
    float* sCs   = biasS + 128;
    float* sCq   = sCs + 128;

    int tid = threadIdx.x;
    int lane = tid & 31, warp = tid >> 5;
    int g = lane >> 2, t = lane & 3;
    int m0 = (warp >> 1) * 32, n0 = (warp & 1) * 64;
    int row0 = blockIdx.x * 128;

    if (tid < 128) { biasS[tid] = bias[tid]; sCs[tid] = 0.f; sCq[tid] = 0.f; }

    float acc[2][8][4];
    #pragma unroll
    for (int i = 0; i < 2; i++)
        #pragma unroll
        for (int j = 0; j < 8; j++)
            { acc[i][j][0]=0.f; acc[i][j][1]=0.f; acc[i][j][2]=0.f; acc[i][j][3]=0.f; }

    const __half* Asrc[3] = { g_h, g_t1, g_t2 };
    const int NCH = 12;
    uint4 aregs[2], anext[2];
    ldg_A16(aregs, Asrc[0], row0, 0);
    load_B_async(sbase, OFF_BS0, W, 0);
    CP_COMMIT();

    for (int i = 0; i < NCH; i++) {
        int abuf = (i & 1) ? OFF_AS1 : OFF_AS0;
        int bbuf = (i & 1) ? OFF_BS1 : OFF_BS0;
        sts_A16(smem + abuf, aregs);
        if (i + 1 < NCH) {
            int j = i + 1;
            ldg_A16(anext, Asrc[j >> 2], row0, j & 3);
            load_B_async(sbase, (j & 1) ? OFF_BS1 : OFF_BS0,
                         W + (size_t)(j >> 2) * HH * HH, j & 3);
            CP_COMMIT();
            CP_WAIT1();
        } else {
            CP_WAIT0();
        }
        __syncthreads();
        mma_chunk(smem + abuf, smem + bbuf, acc, m0, n0, g, t);
        __syncthreads();
        aregs[0] = anext[0];
        aregs[1] = anext[1];
    }

    acc_to_stage(stage, biasS, acc, m0, n0, g, t);
    __syncthreads();

    // store fp16 + per-column BN partials (thread owns column c = tid & 127)
    {
        float ps = 0.f, pq = 0.f;
        int c = tid & 127;
        int rbase = tid >> 7;
        #pragma unroll 4
        for (int k = 0; k < 64; k++) {
            int r = rbase + k * 2;
            int row = row0 + r;
            if (row < NN) {
                float v = stage[r * ST_PITCH + c];
                g_o[(size_t)row * HH + c] = __float2half(v);
                ps += v; pq = fmaf(v, v, pq);
            }
        }
        atomicAdd(&sCs[c], ps);
        atomicAdd(&sCq[c], pq);
    }
    __syncthreads();
    if (tid < 128) {
        atomicAdd(&g_bnsum[tid], sCs[tid]);
        atomicAdd(&g_bnsq[tid],  sCq[tid]);
    }
}

// ---------------- CSR spmm #1: t1 = L_hat h; fused Dirichlet reg (fp16, x4) ----------------
__global__ void __launch_bounds__(256) k_spmm1() {
    __shared__ float blk_ss[8];
    int warp = blockIdx.x * 8 + (threadIdx.x >> 5);
    int lane = threadIdx.x & 31;
    const uint2* H = (const uint2*)g_h;
    float ss = 0.f;
    if (warp < NN) {
        int beg = g_rowptr[warp], end = g_rowptr[warp + 1];
        float4 hd = h2f4(H[(size_t)warp * 32 + lane]);
        float4 acc = make_float4(0.f, 0.f, 0.f, 0.f);
        int e = beg;
        for (; e + 4 <= end; e += 4) {
            int s0 = g_ecol[e],   s1 = g_ecol[e+1];
            int s2 = g_ecol[e+2], s3 = g_ecol[e+3];
            float w0 = g_ew[e],   w1 = g_ew[e+1];
            float w2 = g_ew[e+2], w3 = g_ew[e+3];
            float4 h0 = h2f4(H[(size_t)s0 * 32 + lane]);
            float4 h1 = h2f4(H[(size_t)s1 * 32 + lane]);
            float4 h2 = h2f4(H[(size_t)s2 * 32 + lane]);
            float4 h3 = h2f4(H[(size_t)s3 * 32 + lane]);
            acc.x = fmaf(w0,h0.x,acc.x); acc.y = fmaf(w0,h0.y,acc.y);
            acc.z = fmaf(w0,h0.z,acc.z); acc.w = fmaf(w0,h0.w,acc.w);
            float dx, dy, dz, dw;
            dx=h0.x-hd.x; dy=h0.y-hd.y; dz=h0.z-hd.z; dw=h0.w-hd.w;
            ss=fmaf(dx,dx,ss); ss=fmaf(dy,dy,ss); ss=fmaf(dz,dz,ss); ss=fmaf(dw,dw,ss);
            acc.x = fmaf(w1,h1.x,acc.x); acc.y = fmaf(w1,h1.y,acc.y);
            acc.z = fmaf(w1,h1.z,acc.z); acc.w = fmaf(w1,h1.w,acc.w);
            dx=h1.x-hd.x; dy=h1.y-hd.y; dz=h1.z-hd.z; dw=h1.w-hd.w;
            ss=fmaf(dx,dx,ss); ss=fmaf(dy,dy,ss); ss=fmaf(dz,dz,ss); ss=fmaf(dw,dw,ss);
            acc.x = fmaf(w2,h2.x,acc.x); acc.y = fmaf(w2,h2.y,acc.y);
            acc.z = fmaf(w2,h2.z,acc.z); acc.w = fmaf(w2,h2.w,acc.w);
            dx=h2.x-hd.x; dy=h2.y-hd.y; dz=h2.z-hd.z; dw=h2.w-hd.w;
            ss=fmaf(dx,dx,ss); ss=fmaf(dy,dy,ss); ss=fmaf(dz,dz,ss); ss=fmaf(dw,dw,ss);
            acc.x = fmaf(w3,h3.x,acc.x); acc.y = fmaf(w3,h3.y,acc.y);
            acc.z = fmaf(w3,h3.z,acc.z); acc.w = fmaf(w3,h3.w,acc.w);
            dx=h3.x-hd.x; dy=h3.y-hd.y; dz=h3.z-hd.z; dw=h3.w-hd.w;
            ss=fmaf(dx,dx,ss); ss=fmaf(dy,dy,ss); ss=fmaf(dz,dz,ss); ss=fmaf(dw,dw,ss);
        }
        for (; e < end; e++) {
            int s = g_ecol[e];
            float w = g_ew[e];
            float4 hv = h2f4(H[(size_t)s * 32 + lane]);
            acc.x = fmaf(w,hv.x,acc.x); acc.y = fmaf(w,hv.y,acc.y);
            acc.z = fmaf(w,hv.z,acc.z); acc.w = fmaf(w,hv.w,acc.w);
            float dx=hv.x-hd.x, dy=hv.y-hd.y, dz=hv.z-hd.z, dw=hv.w-hd.w;
            ss=fmaf(dx,dx,ss); ss=fmaf(dy,dy,ss); ss=fmaf(dz,dz,ss); ss=fmaf(dw,dw,ss);
        }
        ((uint2*)g_t1)[(size_t)warp * 32 + lane] = f2h4(acc);
    }
    #pragma unroll
    for (int off = 16; off > 0; off >>= 1)
        ss += __shfl_xor_sync(0xffffffffu, ss, off);
    if (lane == 0) blk_ss[threadIdx.x >> 5] = ss;
    __syncthreads();
    if (threadIdx.x == 0) {
        double tot = 0.0;
        #pragma unroll
        for (int j = 0; j < 8; j++) tot += (double)blk_ss[j];
        atomicAdd(&g_reg, tot);
    }
}

// ---------------- CSR spmm #2: t2 = 2 L_hat t1 - h  (fp16, x4) ----------------
__global__ void __launch_bounds__(256) k_spmm2() {
    int warp = blockIdx.x * 8 + (threadIdx.x >> 5);
    if (warp >= NN) return;
    int lane = threadIdx.x & 31;
    const uint2* T1 = (const uint2*)g_t1;
    int beg = g_rowptr[warp], end = g_rowptr[warp + 1];
    float4 acc = make_float4(0.f, 0.f, 0.f, 0.f);
    int e = beg;
    for (; e + 4 <= end; e += 4) {
        int s0 = g_ecol[e],   s1 = g_ecol[e+1];
        int s2 = g_ecol[e+2], s3 = g_ecol[e+3];
        float w0 = g_ew[e],   w1 = g_ew[e+1];
        float w2 = g_ew[e+2], w3 = g_ew[e+3];
        float4 h0 = h2f4(T1[(size_t)s0 * 32 + lane]);
        float4 h1 = h2f4(T1[(size_t)s1 * 32 + lane]);
        float4 h2 = h2f4(T1[(size_t)s2 * 32 + lane]);
        float4 h3 = h2f4(T1[(size_t)s3 * 32 + lane]);
        acc.x = fmaf(w0,h0.x,acc.x); acc.y = fmaf(w0,h0.y,acc.y);
        acc.z = fmaf(w0,h0.z,acc.z); acc.w = fmaf(w0,h0.w,acc.w);
        acc.x = fmaf(w1,h1.x,acc.x); acc.y = fmaf(w1,h1.y,acc.y);
        acc.z = fmaf(w1,h1.z,acc.z); acc.w = fmaf(w1,h1.w,acc.w);
        acc.x = fmaf(w2,h2.x,acc.x); acc.y = fmaf(w2,h2.y,acc.y);
        acc.z = fmaf(w2,h2.z,acc.z); acc.w = fmaf(w2,h2.w,acc.w);
        acc.x = fmaf(w3,h3.x,acc.x); acc.y = fmaf(w3,h3.y,acc.y);
        acc.z = fmaf(w3,h3.z,acc.z); acc.w = fmaf(w3,h3.w,acc.w);
    }
    for (; e < end; e++) {
        int s = g_ecol[e];
        float w = g_ew[e];
        float4 hv = h2f4(T1[(size_t)s * 32 + lane]);
        acc.x = fmaf(w,hv.x,acc.x); acc.y = fmaf(w,hv.y,acc.y);
        acc.z = fmaf(w,hv.z,acc.z); acc.w = fmaf(w,hv.w,acc.w);
    }
    float4 hd = h2f4(((const uint2*)g_h)[(size_t)warp * 32 + lane]);
    float4 o;
    o.x = 2.f * acc.x - hd.x;
    o.y = 2.f * acc.y - hd.y;
    o.z = 2.f * acc.z - hd.z;
    o.w = 2.f * acc.w - hd.w;
    ((uint2*)g_t2)[(size_t)warp * 32 + lane] = f2h4(o);
}

// ---------------- fused: Dirichlet reg of final h + global mean pool ----------------
__global__ void __launch_bounds__(256) k_regpool(const int* __restrict__ batch) {
    __shared__ float blk_ss[8];
    int warp = blockIdx.x * 8 + (threadIdx.x >> 5);
    int lane = threadIdx.x & 31;
    const uint2* H = (const uint2*)g_h;
    float ss = 0.f;
    if (warp < NN) {
        int beg = g_rowptr[warp], end = g_rowptr[warp + 1];
        float4 hd = h2f4(H[(size_t)warp * 32 + lane]);
        int e = beg;
        for (; e + 4 <= end; e += 4) {
            int s0 = g_ecol[e],   s1 = g_ecol[e+1];
            int s2 = g_ecol[e+2], s3 = g_ecol[e+3];
            float4 h0 = h2f4(H[(size_t)s0 * 32 + lane]);
            float4 h1 = h2f4(H[(size_t)s1 * 32 + lane]);
            float4 h2 = h2f4(H[(size_t)s2 * 32 + lane]);
            float4 h3 = h2f4(H[(size_t)s3 * 32 + lane]);
            float dx, dy, dz, dw;
            dx=h0.x-hd.x; dy=h0.y-hd.y; dz=h0.z-hd.z; dw=h0.w-hd.w;
            ss=fmaf(dx,dx,ss); ss=fmaf(dy,dy,ss); ss=fmaf(dz,dz,ss); ss=fmaf(dw,dw,ss);
            dx=h1.x-hd.x; dy=h1.y-hd.y; dz=h1.z-hd.z; dw=h1.w-hd.w;
            ss=fmaf(dx,dx,ss); ss=fmaf(dy,dy,ss); ss=fmaf(dz,dz,ss); ss=fmaf(dw,dw,ss);
            dx=h2.x-hd.x; dy=h2.y-hd.y; dz=h2.z-hd.z; dw=h2.w-hd.w;
            ss=fmaf(dx,dx,ss); ss=fmaf(dy,dy,ss); ss=fmaf(dz,dz,ss); ss=fmaf(dw,dw,ss);
            dx=h3.x-hd.x; dy=h3.y-hd.y; dz=h3.z-hd.z; dw=h3.w-hd.w;
            ss=fmaf(dx,dx,ss); ss=fmaf(dy,dy,ss); ss=fmaf(dz,dz,ss); ss=fmaf(dw,dw,ss);
        }
        for (; e < end; e++) {
            int s = g_ecol[e];
            float4 hv = h2f4(H[(size_t)s * 32 + lane]);
            float dx=hv.x-hd.x, dy=hv.y-hd.y, dz=hv.z-hd.z, dw=hv.w-hd.w;
            ss=fmaf(dx,dx,ss); ss=fmaf(dy,dy,ss); ss=fmaf(dz,dz,ss); ss=fmaf(dw,dw,ss);
        }
        // pool
        int b = batch[warp];
        float* gp = &g_gsum[(size_t)b * HH + lane * 4];
        atomicAdd(gp + 0, hd.x);
        atomicAdd(gp + 1, hd.y);
        atomicAdd(gp + 2, hd.z);
        atomicAdd(gp + 3, hd.w);
        if (lane == 0) atomicAdd(&g_gcnt[b], 1.f);
    }
    #pragma unroll
    for (int off = 16; off > 0; off >>= 1)
        ss += __shfl_xor_sync(0xffffffffu, ss, off);
    if (lane == 0) blk_ss[threadIdx.x >> 5] = ss;
    __syncthreads();
    if (threadIdx.x == 0) {
        double tot = 0.0;
        #pragma unroll
        for (int j = 0; j < 8; j++) tot += (double)blk_ss[j];
        atomicAdd(&g_reg, tot);
    }
}

// ---------------- BN finalize + apply ----------------
__global__ void k_bnfin(const float* __restrict__ bng, const float* __restrict__ bnb) {
    int c = threadIdx.x;
    float m = g_bnsum[c] * (1.f / NN);
    float v = g_bnsq[c] * (1.f / NN) - m * m;
    float sc = bng[c] * rsqrtf(v + EPSF);
    g_bnscale[c] = sc;
    g_bnshift[c] = bnb[c] - m * sc;
    g_bnsum[c] = 0.f;
    g_bnsq[c]  = 0.f;
}

__global__ void k_bnapply() {
    int i = blockIdx.x * blockDim.x + threadIdx.x;   // uint2 index over NN*32
    int c4 = i & 31;
    float4 v  = h2f4(((const uint2*)g_o)[i]);
    float4 sc = ((const float4*)g_bnscale)[c4];
    float4 sh = ((const float4*)g_bnshift)[c4];
    float4 o;
    o.x = fmaxf(fmaf(v.x, sc.x, sh.x), 0.f);
    o.y = fmaxf(fmaf(v.y, sc.y, sh.y), 0.f);
    o.z = fmaxf(fmaf(v.z, sc.z, sh.z), 0.f);
    o.w = fmaxf(fmaf(v.w, sc.w, sh.w), 0.f);
    ((uint2*)g_h)[i] = f2h4(o);
}

// ---------------- MLP head + output ----------------
__global__ void k_head(const float* __restrict__ w1, const float* __restrict__ b1,
                       const float* __restrict__ w2, const float* __restrict__ b2,
                       float* __restrict__ out, int out_size)
{
    __shared__ float gm[HH];
    __shared__ float zz[64];
    int g = blockIdx.x, t = threadIdx.x;
    float cnt = fmaxf(g_gcnt[g], 1.f);
    gm[t] = g_gsum[(size_t)g * HH + t] / cnt;
    __syncthreads();
    if (t < 64) {
        float a = b1[t];
        #pragma unroll 4
        for (int c = 0; c < HH; c++) a = fmaf(gm[c], w1[c * 64 + t], a);
        zz[t] = fmaxf(a, 0.f);
    }
    __syncthreads();
    if (t < 2) {
        float a = b2[t];
        #pragma unroll 4
        for (int k = 0; k < 64; k++) a = fmaf(zz[k], w2[k * 2 + t], a);
        out[g * 2 + t] = a;
    }
    if (g == 0 && t == 0 && out_size > 256)
        out[256] = (float)(g_reg / (4.0 * (double)EE));
}

// ---------------- launch ----------------
extern "C" void kernel_launch(void* const* d_in, const int* in_sizes, int n_in,
                              void* d_out, int out_size)
{
    const float* x      = (const float*)d_in[0];
    const float* w_in   = (const float*)d_in[1];
    const float* b_in   = (const float*)d_in[2];
    const float* ln_g   = (const float*)d_in[3];
    const float* ln_b   = (const float*)d_in[4];
    const float* cheb_w = (const float*)d_in[5];
    const float* cheb_b = (const float*)d_in[6];
    const float* bn_g   = (const float*)d_in[7];
    const float* bn_b   = (const float*)d_in[8];
    const float* w1     = (const float*)d_in[9];
    const float* b1     = (const float*)d_in[10];
    const float* w2     = (const float*)d_in[11];
    const float* b2     = (const float*)d_in[12];
    const int* ei       = (const int*)d_in[13];
    const int* batch    = (const int*)d_in[14];
    float* out = (float*)d_out;

    cudaFuncSetAttribute(k_embed_mma, cudaFuncAttributeMaxDynamicSharedMemorySize, SMEM_DYN);
    cudaFuncSetAttribute(k_cheb_mma,  cudaFuncAttributeMaxDynamicSharedMemorySize, SMEM_DYN);

    const int FB = NN * 32 / 256;            // 6250 (uint2 elements / 256)
    const int NODE_WARP_BLKS = (NN + 7) / 8; // 6250

    k_init<<<(NN + 255) / 256, 256>>>();
    k_edge_prep<<<EE / 256, 256>>>(ei);
    k_dinv<<<(NN + 255) / 256, 256>>>();
    k_scan1<<<NBLK, SCAN_B>>>();
    k_scan2<<<1, SCAN_B>>>();
    k_scan3<<<NBLK, SCAN_B>>>();
    k_scatter<<<EE / 256, 256>>>();

    k_embed_mma<<<NTILE, 256, SMEM_DYN>>>(x, w_in, b_in, ln_g, ln_b);

    for (int l = 0; l < LL; l++) {
        k_spmm1<<<NODE_WARP_BLKS, 256>>>();
        k_spmm2<<<NODE_WARP_BLKS, 256>>>();
        k_cheb_mma<<<NTILE, 256, SMEM_DYN>>>(cheb_w + (size_t)l * KK * HH * HH,
                                             cheb_b + (size_t)l * HH);
        k_bnfin<<<1, HH>>>(bn_g + (size_t)l * HH, bn_b + (size_t)l * HH);
        k_bnapply<<<FB, 256>>>();
    }

    k_regpool<<<NODE_WARP_BLKS, 256>>>(batch);
    k_head<<<GG, HH>>>(w1, b1, w2, b2, out, out_size);
}